// round 13
// baseline (speedup 1.0000x reference)
#include <cuda_runtime.h>
#include <cuda_bf16.h>
#include <math.h>
#include <cstdint>

#define HWS  4096
#define TOK  40960
#define QKV_HALF (TOK*384)

// ---------------------------------------------------------------------------
// Static device scratch
// ---------------------------------------------------------------------------
__device__ __nv_bfloat16 g_xn_bf [TOK*256];
__device__ __nv_bfloat16 g_qkv_bf[2*QKV_HALF];
__device__ __nv_bfloat16 g_ao_bf [TOK*256];
__device__ float         g_yT    [TOK*256];
__device__ __nv_bfloat16 g_tn_bf [TOK*256];
__device__ __nv_bfloat16 g_hid_bf[TOK*1024];
__device__ __nv_bfloat16 g_wh[384*128];
__device__ __nv_bfloat16 g_wv[384*128];
__device__ __nv_bfloat16 g_wf[256*256];
__device__ __nv_bfloat16 g_w1[1024*256];
__device__ __nv_bfloat16 g_w2[256*1024];

#define SMEM_SWIZZLE_128B(byte_offset) \
    ((byte_offset) ^ (((byte_offset) >> 3) & 0x70))

#define SMEM_DYN128 98304     // 3 stages x (16KB A + 16KB B)

// ---------------------------------------------------------------------------
// Baseline-ISA building blocks
// ---------------------------------------------------------------------------
__device__ __forceinline__ void mma16816(float d[4], const uint32_t a[4],
                                         uint32_t b0, uint32_t b1)
{
    asm volatile(
        "mma.sync.aligned.m16n8k16.row.col.f32.bf16.bf16.f32 "
        "{%0,%1,%2,%3},{%4,%5,%6,%7},{%8,%9},{%0,%1,%2,%3};"
        : "+f"(d[0]), "+f"(d[1]), "+f"(d[2]), "+f"(d[3])
        : "r"(a[0]), "r"(a[1]), "r"(a[2]), "r"(a[3]), "r"(b0), "r"(b1));
}
__device__ __forceinline__ void ldsm_x4(uint32_t r[4], uint32_t addr)
{
    asm volatile("ldmatrix.sync.aligned.m8n8.x4.shared.b16 {%0,%1,%2,%3}, [%4];"
        : "=r"(r[0]), "=r"(r[1]), "=r"(r[2]), "=r"(r[3]) : "r"(addr));
}
__device__ __forceinline__ void cp_async16(uint32_t saddr, const void* g)
{
    asm volatile("cp.async.cg.shared.global [%0], [%1], 16;" :: "r"(saddr), "l"(g));
}
__device__ __forceinline__ void cp_async16_ca(uint32_t saddr, const void* g)
{
    asm volatile("cp.async.ca.shared.global [%0], [%1], 16;" :: "r"(saddr), "l"(g));
}
__device__ __forceinline__ void cp_commit()
{
    asm volatile("cp.async.commit_group;");
}
template<int N> __device__ __forceinline__ void cp_wait()
{
    asm volatile("cp.async.wait_group %0;" :: "n"(N));
}
__device__ __forceinline__ uint32_t smem_u32(const void* p)
{
    uint32_t a;
    asm("{ .reg .u64 t; cvta.to.shared.u64 t, %1; cvt.u32.u64 %0, t; }"
        : "=r"(a) : "l"(p));
    return a;
}
// Fast GELU (tanh form via single __expf). Branch-free, saturates correctly.
__device__ __forceinline__ float gelu_fast(float h)
{
    float u = 0.7978845608028654f * (h + 0.044715f * h * h * h);
    float t = 1.f - 2.f / (__expf(2.f * u) + 1.f);
    return 0.5f * h * (1.f + t);
}

// ---------------------------------------------------------------------------
// 128x128 warp-MMA GEMM (8 warps @ 64x32), 3-stage cp.async, .ca weights.
// ---------------------------------------------------------------------------
__device__ __forceinline__ void wgemm(
    const __nv_bfloat16* __restrict__ A, int lda,
    const __nv_bfloat16* __restrict__ B, int ldb,
    int m0, int n0, int nchunks, uint32_t sbase,
    float (&acc)[4][4][4])
{
    const int tid  = threadIdx.x;
    const int lane = tid & 31;
    const int w    = tid >> 5;
    const int wm   = (w & 1) * 64;
    const int wn   = (w >> 1) * 32;
    const int r_ld = tid >> 3;
    const int cc_ld = tid & 7;

    const int a_row = (lane & 7) + ((lane >> 3) & 1) * 8;
    const int a_k16 = ((lane >> 4) & 1) * 16;
    const int b_row = (lane & 7) + ((lane >> 4) & 1) * 8;
    const int b_k16 = ((lane >> 3) & 1) * 16;

    #pragma unroll
    for (int fm = 0; fm < 4; fm++)
        #pragma unroll
        for (int fn = 0; fn < 4; fn++)
            #pragma unroll
            for (int i = 0; i < 4; i++) acc[fm][fn][i] = 0.f;

    auto issue = [&](int c) {
        int s = c % 3;
        int k0 = c << 6;
        uint32_t base = sbase + s * 32768;
        uint32_t off = SMEM_SWIZZLE_128B((uint32_t)(r_ld * 128 + cc_ld * 16));
        #pragma unroll
        for (int it = 0; it < 4; it++) {
            int r = it * 32 + r_ld;
            cp_async16(base + it * 4096 + off,
                       A + (size_t)(m0 + r) * lda + k0 + cc_ld * 8);
            cp_async16_ca(base + 16384 + it * 4096 + off,
                          B + (size_t)(n0 + r) * ldb + k0 + cc_ld * 8);
        }
        cp_commit();
    };

    issue(0);
    if (nchunks > 1) issue(1);

    for (int c = 0; c < nchunks; c++) {
        if (c + 2 < nchunks) { issue(c + 2); cp_wait<2>(); }
        else if (c + 1 < nchunks) cp_wait<1>();
        else cp_wait<0>();
        __syncthreads();

        uint32_t Ab = sbase + (c % 3) * 32768;
        uint32_t Bb = Ab + 16384;
        #pragma unroll
        for (int ks = 0; ks < 4; ks++) {
            int kb = ks * 32;
            uint32_t a[4][4];
            #pragma unroll
            for (int fm = 0; fm < 4; fm++) {
                int r = wm + fm * 16 + a_row;
                ldsm_x4(a[fm], Ab + SMEM_SWIZZLE_128B((uint32_t)(r * 128 + kb + a_k16)));
            }
            uint32_t bfr[2][4];
            #pragma unroll
            for (int fp = 0; fp < 2; fp++) {
                int rn = wn + fp * 16 + b_row;
                ldsm_x4(bfr[fp], Bb + SMEM_SWIZZLE_128B((uint32_t)(rn * 128 + kb + b_k16)));
            }
            #pragma unroll
            for (int fn = 0; fn < 4; fn++) {
                uint32_t b0 = bfr[fn >> 1][(fn & 1) * 2];
                uint32_t b1 = bfr[fn >> 1][(fn & 1) * 2 + 1];
                #pragma unroll
                for (int fm = 0; fm < 4; fm++)
                    mma16816(acc[fm][fn], a[fm], b0, b1);
            }
        }
        __syncthreads();
    }
}

// ---------------------------------------------------------------------------
// LN1
// ---------------------------------------------------------------------------
__global__ __launch_bounds__(256) void ln1_kernel(
    const float* __restrict__ x,
    const float* __restrict__ gam,
    const float* __restrict__ bet)
{
    __shared__ float sm[256][33];
    __shared__ float psum[8][32], psq[8][32];
    __shared__ float mu[32], rs[32];

    int bf  = blockIdx.y;
    int hw0 = blockIdx.x * 32;
    int tid = threadIdx.x;
    int tx  = tid & 31, ty = tid >> 5;

    const float* xp = x + (size_t)bf * 256 * HWS;
    #pragma unroll
    for (int c0 = 0; c0 < 256; c0 += 8) {
        int c = c0 + ty;
        sm[c][tx] = xp[(size_t)c * HWS + hw0 + tx];
    }
    __syncthreads();

    float s = 0.f, sq = 0.f;
    #pragma unroll
    for (int k = 0; k < 32; k++) {
        float v = sm[ty * 32 + k][tx];
        s += v; sq += v * v;
    }
    psum[ty][tx] = s; psq[ty][tx] = sq;
    __syncthreads();

    if (ty == 0) {
        float S = 0.f, Q = 0.f;
        #pragma unroll
        for (int k = 0; k < 8; k++) { S += psum[k][tx]; Q += psq[k][tx]; }
        float m   = S * (1.f / 256.f);
        float var = Q * (1.f / 256.f) - m * m;
        mu[tx] = m;
        rs[tx] = rsqrtf(var + 1e-5f);
    }
    __syncthreads();

    int tokl = tid >> 3, cg = tid & 7;
    int tok  = bf * HWS + hw0 + tokl;
    float m = mu[tokl], r = rs[tokl];
    size_t rowoff = (size_t)tok * 256;
    #pragma unroll
    for (int k = 0; k < 32; k++) {
        int c = k * 8 + cg;
        float v = sm[c][tokl];
        g_xn_bf[rowoff + c] = __float2bfloat16_rn((v - m) * r * gam[c] + bet[c]);
    }
}

// ---------------------------------------------------------------------------
__global__ __launch_bounds__(256) void cvt_all(
    const float* __restrict__ wh, const float* __restrict__ wv,
    const float* __restrict__ wf, const float* __restrict__ w1,
    const float* __restrict__ w2)
{
    int i = blockIdx.x * 256 + threadIdx.x;
    if (i < 49152)        g_wh[i]          = __float2bfloat16_rn(wh[i]);
    else if (i < 98304)   g_wv[i - 49152]  = __float2bfloat16_rn(wv[i - 49152]);
    else if (i < 163840)  g_wf[i - 98304]  = __float2bfloat16_rn(wf[i - 98304]);
    else if (i < 425984)  g_w1[i - 163840] = __float2bfloat16_rn(w1[i - 163840]);
    else if (i < 688128)  g_w2[i - 425984] = __float2bfloat16_rn(w2[i - 425984]);
}

// ---------------------------------------------------------------------------
// QKV GEMM -> token-major g_qkv_bf[branch][t][384]
// ---------------------------------------------------------------------------
__global__ __launch_bounds__(256, 2) void qkv_mm(
    const float* __restrict__ bh, const float* __restrict__ bv)
{
    extern __shared__ __align__(1024) char dsm[];
    uint32_t sbase = smem_u32(dsm);
    int branch = blockIdx.z;
    int m0 = blockIdx.y * 128, n0 = blockIdx.x * 128;
    const __nv_bfloat16* A = g_xn_bf + branch * 128;
    const __nv_bfloat16* W = branch ? g_wv : g_wh;
    const float* bias = branch ? bv : bh;

    float acc[4][4][4];
    wgemm(A, 256, W, 128, m0, n0, 2, sbase, acc);

    const int lane = threadIdx.x & 31, w = threadIdx.x >> 5;
    const int wm = (w & 1) * 64, wn = (w >> 1) * 32;
    const int g = lane >> 2, tq = lane & 3;
    #pragma unroll
    for (int fm = 0; fm < 4; fm++)
        #pragma unroll
        for (int i2 = 0; i2 < 2; i2++) {
            int ml = wm + fm * 16 + g + i2 * 8;
            #pragma unroll
            for (int fn = 0; fn < 4; fn++) {
                int ol = wn + fn * 8 + tq * 2;
                int o  = n0 + ol;
                float v0 = acc[fm][fn][i2 * 2]     + __ldg(bias + o);
                float v1 = acc[fm][fn][i2 * 2 + 1] + __ldg(bias + o + 1);
                __nv_bfloat162 p = __floats2bfloat162_rn(v0, v1);
                *(uint32_t*)(dsm + ml * 272 + ol * 2) = *(uint32_t*)&p;
            }
        }
    __syncthreads();

    int row = threadIdx.x >> 1, half = threadIdx.x & 1;
    size_t t = (size_t)m0 + row;
    __nv_bfloat16* dst = g_qkv_bf + (size_t)branch * QKV_HALF + t * 384 + n0 + half * 64;
    const char* src = dsm + row * 272 + half * 128;
    #pragma unroll
    for (int j = 0; j < 8; j++)
        *(uint4*)(dst + j * 8) = *(const uint4*)(src + j * 16);
}

// ---------------------------------------------------------------------------
// Attention
// ---------------------------------------------------------------------------
__global__ __launch_bounds__(256) void attn_kernel()
{
    int id   = blockIdx.x;
    int dir  = id >> 10;
    int b    = (id >> 9) & 1;
    int n    = (id >> 6) & 7;
    int l    = id & 63;

    int tid = threadIdx.x;
    int dd  = tid >> 2;
    int dq  = (tid & 3) * 4;

    const __nv_bfloat16* buf = g_qkv_bf + (size_t)dir * QKV_HALF;
    int hw = dir ? dd * 64 + l : l * 64 + dd;
    int oq = n * 16 + dq;

    float4 q[5], k[5];
    #pragma unroll
    for (int i = 0; i < 5; i++) {
        size_t t = ((size_t)(b * 5 + i) * 4096 + hw) * 384;
        uint2 rq = *reinterpret_cast<const uint2*>(buf + t + oq);
        uint2 rk = *reinterpret_cast<const uint2*>(buf + t + 128 + oq);
        float2 q0 = __bfloat1622float2(*reinterpret_cast<__nv_bfloat162*>(&rq.x));
        float2 q1 = __bfloat1622float2(*reinterpret_cast<__nv_bfloat162*>(&rq.y));
        float2 k0 = __bfloat1622float2(*reinterpret_cast<__nv_bfloat162*>(&rk.x));
        float2 k1 = __bfloat1622float2(*reinterpret_cast<__nv_bfloat162*>(&rk.y));
        q[i] = make_float4(q0.x, q0.y, q1.x, q1.y);
        k[i] = make_float4(k0.x, k0.y, k1.x, k1.y);
    }
    float p[25];
    #pragma unroll
    for (int i = 0; i < 5; i++)
        #pragma unroll
        for (int j = 0; j < 5; j++) {
            float4 a = q[i], c = k[j];
            p[i*5+j] = a.x*c.x + a.y*c.y + a.z*c.z + a.w*c.w;
        }

    __shared__ float red[25][8];
    #pragma unroll
    for (int e = 0; e < 25; e++) {
        float v = p[e];
        #pragma unroll
        for (int off = 16; off; off >>= 1) v += __shfl_down_sync(0xffffffffu, v, off);
        if ((tid & 31) == 0) red[e][tid >> 5] = v;
    }
    __syncthreads();

    __shared__ float P[5][5];
    if (tid < 5) {
        float srow[5];
        float mx = -1e30f;
        #pragma unroll
        for (int j = 0; j < 5; j++) {
            float s = 0.f;
            #pragma unroll
            for (int wdx = 0; wdx < 8; wdx++) s += red[tid*5+j][wdx];
            s *= (1.f / 32.f);
            srow[j] = s; mx = fmaxf(mx, s);
        }
        float se = 0.f;
        #pragma unroll
        for (int j = 0; j < 5; j++) { srow[j] = __expf(srow[j] - mx); se += srow[j]; }
        float inv = 1.f / se;
        #pragma unroll
        for (int j = 0; j < 5; j++) P[tid][j] = srow[j] * inv;
    }
    __syncthreads();

    float4 o[5];
    #pragma unroll
    for (int i = 0; i < 5; i++) o[i] = make_float4(0.f, 0.f, 0.f, 0.f);
    #pragma unroll
    for (int j = 0; j < 5; j++) {
        size_t t = ((size_t)(b * 5 + j) * 4096 + hw) * 384;
        uint2 rv = *reinterpret_cast<const uint2*>(buf + t + 256 + oq);
        float2 v0 = __bfloat1622float2(*reinterpret_cast<__nv_bfloat162*>(&rv.x));
        float2 v1 = __bfloat1622float2(*reinterpret_cast<__nv_bfloat162*>(&rv.y));
        #pragma unroll
        for (int i = 0; i < 5; i++) {
            float pij = P[i][j];
            o[i].x = fmaf(pij, v0.x, o[i].x);
            o[i].y = fmaf(pij, v0.y, o[i].y);
            o[i].z = fmaf(pij, v1.x, o[i].z);
            o[i].w = fmaf(pij, v1.y, o[i].w);
        }
    }

    int c = dir ? (128 + n * 16 + dq) : (n * 16 + dq);
    #pragma unroll
    for (int fi = 0; fi < 5; fi++) {
        size_t tok = (size_t)(b * 5 + fi) * 4096 + hw;
        __nv_bfloat162 lo = __floats2bfloat162_rn(o[fi].x, o[fi].y);
        __nv_bfloat162 hi = __floats2bfloat162_rn(o[fi].z, o[fi].w);
        uint2 packed;
        packed.x = *reinterpret_cast<uint32_t*>(&lo);
        packed.y = *reinterpret_cast<uint32_t*>(&hi);
        *reinterpret_cast<uint2*>(g_ao_bf + tok * 256 + c) = packed;
    }
}

// ---------------------------------------------------------------------------
// Output projection + residual: y = ao @ wf^T + bf + x (fp32, channel-major)
// ---------------------------------------------------------------------------
__global__ __launch_bounds__(256, 2) void proj_mm(
    const float* __restrict__ x, const float* __restrict__ bfp)
{
    extern __shared__ __align__(1024) char dsm[];
    uint32_t sbase = smem_u32(dsm);
    int m0 = blockIdx.y * 128, n0 = blockIdx.x * 128;
    int bfi = m0 >> 12, hw0 = m0 & 4095;

    float acc[4][4][4];
    wgemm(g_ao_bf, 256, g_wf, 256, m0, n0, 4, sbase, acc);

    float* Rs = reinterpret_cast<float*>(dsm);
    {
        int tid = threadIdx.x;
        #pragma unroll
        for (int it = 0; it < 16; it++) {
            int idx = it * 256 + tid;
            int c = idx >> 5, hw4 = idx & 31;
            float4 v = *reinterpret_cast<const float4*>(
                x + ((size_t)bfi * 256 + n0 + c) * 4096 + hw0 + hw4 * 4);
            *reinterpret_cast<float4*>(Rs + c * 132 + hw4 * 4) = v;
        }
    }
    __syncthreads();

    const int lane = threadIdx.x & 31, w = threadIdx.x >> 5;
    const int wm = (w & 1) * 64, wn = (w >> 1) * 32;
    const int g = lane >> 2, tq = lane & 3;
    #pragma unroll
    for (int fm = 0; fm < 4; fm++)
        #pragma unroll
        for (int fn = 0; fn < 4; fn++) {
            int ol = wn + fn * 8 + tq * 2;
            float b0 = __ldg(bfp + n0 + ol), b1 = __ldg(bfp + n0 + ol + 1);
            #pragma unroll
            for (int i2 = 0; i2 < 2; i2++) {
                int ml = wm + fm * 16 + g + i2 * 8;
                Rs[ol * 132 + ml]       += acc[fm][fn][i2*2]   + b0;
                Rs[(ol + 1) * 132 + ml] += acc[fm][fn][i2*2+1] + b1;
            }
        }
    __syncthreads();

    {
        int tid = threadIdx.x;
        #pragma unroll
        for (int it = 0; it < 16; it++) {
            int idx = it * 256 + tid;
            int c = idx >> 5, hw4 = idx & 31;
            float4 v = *reinterpret_cast<const float4*>(Rs + c * 132 + hw4 * 4);
            *reinterpret_cast<float4*>(
                g_yT + ((size_t)bfi * 256 + n0 + c) * 4096 + hw0 + hw4 * 4) = v;
        }
    }
}

// ---------------------------------------------------------------------------
// LN2: g_yT (channel-major fp32) -> g_tn_bf (token-major bf16).
// ---------------------------------------------------------------------------
__global__ __launch_bounds__(256) void ln2_kernel(
    const float* __restrict__ gam, const float* __restrict__ bet)
{
    __shared__ float sm[256][33];
    __shared__ float psum[8][32], psq[8][32];
    __shared__ float mu[32], rs[32];

    int bf  = blockIdx.y;
    int hw0 = blockIdx.x * 32;
    int tid = threadIdx.x;
    int tx  = tid & 31, ty = tid >> 5;

    const float* yp = g_yT + (size_t)bf * 256 * HWS;
    #pragma unroll
    for (int c0 = 0; c0 < 256; c0 += 8) {
        int c = c0 + ty;
        sm[c][tx] = yp[(size_t)c * HWS + hw0 + tx];
    }
    __syncthreads();

    float s = 0.f, sq = 0.f;
    #pragma unroll
    for (int k = 0; k < 32; k++) {
        float v = sm[ty * 32 + k][tx];
        s += v; sq += v * v;
    }
    psum[ty][tx] = s; psq[ty][tx] = sq;
    __syncthreads();

    if (ty == 0) {
        float S = 0.f, Q = 0.f;
        #pragma unroll
        for (int k = 0; k < 8; k++) { S += psum[k][tx]; Q += psq[k][tx]; }
        float m   = S * (1.f / 256.f);
        float var = Q * (1.f / 256.f) - m * m;
        mu[tx] = m;
        rs[tx] = rsqrtf(var + 1e-5f);
    }
    __syncthreads();

    int tokl = tid >> 3, cg = tid & 7;
    int tok  = bf * HWS + hw0 + tokl;
    float m = mu[tokl], r = rs[tokl];
    size_t rowoff = (size_t)tok * 256;
    #pragma unroll
    for (int k = 0; k < 32; k++) {
        int c = k * 8 + cg;
        float v = sm[c][tokl];
        g_tn_bf[rowoff + c] = __float2bfloat16_rn((v - m) * r * gam[c] + bet[c]);
    }
}

// ---------------------------------------------------------------------------
// MLP GEMM1 + fast GELU -> g_hid_bf (bf16 token-major)
// ---------------------------------------------------------------------------
__global__ __launch_bounds__(256, 2) void mlp1_mm(const float* __restrict__ b1)
{
    extern __shared__ __align__(1024) char dsm[];
    uint32_t sbase = smem_u32(dsm);
    int m0 = blockIdx.y * 128, n0 = blockIdx.x * 128;

    float acc[4][4][4];
    wgemm(g_tn_bf, 256, g_w1, 256, m0, n0, 4, sbase, acc);

    const int lane = threadIdx.x & 31, w = threadIdx.x >> 5;
    const int wm = (w & 1) * 64, wn = (w >> 1) * 32;
    const int g = lane >> 2, tq = lane & 3;
    #pragma unroll
    for (int fm = 0; fm < 4; fm++)
        #pragma unroll
        for (int i2 = 0; i2 < 2; i2++) {
            int ml = wm + fm * 16 + g + i2 * 8;
            #pragma unroll
            for (int fn = 0; fn < 4; fn++) {
                int ol = wn + fn * 8 + tq * 2;
                int o  = n0 + ol;
                float h0 = acc[fm][fn][i2 * 2]     + __ldg(b1 + o);
                float h1 = acc[fm][fn][i2 * 2 + 1] + __ldg(b1 + o + 1);
                __nv_bfloat162 p = __floats2bfloat162_rn(gelu_fast(h0), gelu_fast(h1));
                *(uint32_t*)(dsm + ml * 272 + ol * 2) = *(uint32_t*)&p;
            }
        }
    __syncthreads();

    int row = threadIdx.x >> 1, half = threadIdx.x & 1;
    __nv_bfloat16* dst = g_hid_bf + (size_t)(m0 + row) * 1024 + n0 + half * 64;
    const char* src = dsm + row * 272 + half * 128;
    #pragma unroll
    for (int j = 0; j < 8; j++)
        *(uint4*)(dst + j * 8) = *(const uint4*)(src + j * 16);
}

// ---------------------------------------------------------------------------
// MLP GEMM2 + residual (g_yT) + channel-major store to out (B,F,C,H,W)
// ---------------------------------------------------------------------------
__global__ __launch_bounds__(256, 2) void mlp2_mm(
    const float* __restrict__ b2, float* __restrict__ out)
{
    extern __shared__ __align__(1024) char dsm[];
    uint32_t sbase = smem_u32(dsm);
    int m0 = blockIdx.y * 128, n0 = blockIdx.x * 128;
    int bfi = m0 >> 12, hw0 = m0 & 4095;

    float acc[4][4][4];
    wgemm(g_hid_bf, 1024, g_w2, 1024, m0, n0, 16, sbase, acc);

    float* Rs = reinterpret_cast<float*>(dsm);
    {
        int tid = threadIdx.x;
        #pragma unroll
        for (int it = 0; it < 16; it++) {
            int idx = it * 256 + tid;
            int c = idx >> 5, hw4 = idx & 31;
            float4 v = *reinterpret_cast<const float4*>(
                g_yT + ((size_t)bfi * 256 + n0 + c) * 4096 + hw0 + hw4 * 4);
            *reinterpret_cast<float4*>(Rs + c * 132 + hw4 * 4) = v;
        }
    }
    __syncthreads();

    const int lane = threadIdx.x & 31, w = threadIdx.x >> 5;
    const int wm = (w & 1) * 64, wn = (w >> 1) * 32;
    const int g = lane >> 2, tq = lane & 3;
    #pragma unroll
    for (int fm = 0; fm < 4; fm++)
        #pragma unroll
        for (int fn = 0; fn < 4; fn++) {
            int ol = wn + fn * 8 + tq * 2;
            float b0 = __ldg(b2 + n0 + ol), b1 = __ldg(b2 + n0 + ol + 1);
            #pragma unroll
            for (int i2 = 0; i2 < 2; i2++) {
                int ml = wm + fm * 16 + g + i2 * 8;
                Rs[ol * 132 + ml]       += acc[fm][fn][i2*2]   + b0;
                Rs[(ol + 1) * 132 + ml] += acc[fm][fn][i2*2+1] + b1;
            }
        }
    __syncthreads();

    {
        int tid = threadIdx.x;
        #pragma unroll
        for (int it = 0; it < 16; it++) {
            int idx = it * 256 + tid;
            int c = idx >> 5, hw4 = idx & 31;
            float4 v = *reinterpret_cast<const float4*>(Rs + c * 132 + hw4 * 4);
            *reinterpret_cast<float4*>(
                out + ((size_t)bfi * 256 + n0 + c) * 4096 + hw0 + hw4 * 4) = v;
        }
    }
}

// ---------------------------------------------------------------------------
extern "C" void kernel_launch(void* const* d_in, const int* in_sizes, int n_in,
                              void* d_out, int out_size)
{
    const float* x     = (const float*)d_in[0];
    const float* ln1_g = (const float*)d_in[1];
    const float* ln1_b = (const float*)d_in[2];
    const float* wh    = (const float*)d_in[3];
    const float* bh    = (const float*)d_in[4];
    const float* wv    = (const float*)d_in[5];
    const float* bv    = (const float*)d_in[6];
    const float* wf    = (const float*)d_in[7];
    const float* bf    = (const float*)d_in[8];
    const float* ln2_g = (const float*)d_in[9];
    const float* ln2_b = (const float*)d_in[10];
    const float* w1    = (const float*)d_in[11];
    const float* b1    = (const float*)d_in[12];
    const float* w2    = (const float*)d_in[13];
    const float* b2    = (const float*)d_in[14];
    float* out = (float*)d_out;

    cudaFuncSetAttribute(qkv_mm,  cudaFuncAttributeMaxDynamicSharedMemorySize, SMEM_DYN128);
    cudaFuncSetAttribute(proj_mm, cudaFuncAttributeMaxDynamicSharedMemorySize, SMEM_DYN128);
    cudaFuncSetAttribute(mlp1_mm, cudaFuncAttributeMaxDynamicSharedMemorySize, SMEM_DYN128);
    cudaFuncSetAttribute(mlp2_mm, cudaFuncAttributeMaxDynamicSharedMemorySize, SMEM_DYN128);

    cvt_all<<<2688, 256>>>(wh, wv, wf, w1, w2);
    ln1_kernel<<<dim3(128, 10), 256>>>(x, ln1_g, ln1_b);
    qkv_mm    <<<dim3(3, 320, 2), 256, SMEM_DYN128>>>(bh, bv);
    attn_kernel<<<2048, 256>>>();
    proj_mm   <<<dim3(2, 320), 256, SMEM_DYN128>>>(x, bf);
    ln2_kernel<<<dim3(128, 10), 256>>>(ln2_g, ln2_b);
    mlp1_mm   <<<dim3(8, 320), 256, SMEM_DYN128>>>(b1);
    mlp2_mm   <<<dim3(2, 320), 256, SMEM_DYN128>>>(b2, out);
}

// round 14
// speedup vs baseline: 1.0408x; 1.0408x over previous
#include <cuda_runtime.h>
#include <cuda_bf16.h>
#include <math.h>
#include <cstdint>

#define HWS  4096
#define TOK  40960
#define QKV_HALF (TOK*384)

// ---------------------------------------------------------------------------
// Static device scratch
// ---------------------------------------------------------------------------
__device__ __nv_bfloat16 g_xn_bf [TOK*256];    // LN1 out (bf16, token-major)
__device__ __nv_bfloat16 g_qkv_bf[2*QKV_HALF]; // qkv token-major [branch][t][384]
__device__ __nv_bfloat16 g_ao_bf [TOK*256];    // attention out (bf16 token-major)
__device__ float         g_yT    [TOK*256];    // y channel-major [bf][c][hw] fp32
__device__ __nv_bfloat16 g_tn_bf [TOK*256];    // LN2 out (bf16 token-major)
__device__ __nv_bfloat16 g_hid_bf[TOK*1024];   // MLP hidden (bf16)
__device__ __nv_bfloat16 g_wh[384*128];
__device__ __nv_bfloat16 g_wv[384*128];
__device__ __nv_bfloat16 g_wf[256*256];
__device__ __nv_bfloat16 g_w1[1024*256];
__device__ __nv_bfloat16 g_w2[256*1024];

#define SMEM_SWIZZLE_128B(byte_offset) \
    ((byte_offset) ^ (((byte_offset) >> 3) & 0x70))

#define SMEM_DYN128 98304     // 3 stages x (16KB A + 16KB B)

// ---------------------------------------------------------------------------
// Baseline-ISA building blocks
// ---------------------------------------------------------------------------
__device__ __forceinline__ void mma16816(float d[4], const uint32_t a[4],
                                         uint32_t b0, uint32_t b1)
{
    asm volatile(
        "mma.sync.aligned.m16n8k16.row.col.f32.bf16.bf16.f32 "
        "{%0,%1,%2,%3},{%4,%5,%6,%7},{%8,%9},{%0,%1,%2,%3};"
        : "+f"(d[0]), "+f"(d[1]), "+f"(d[2]), "+f"(d[3])
        : "r"(a[0]), "r"(a[1]), "r"(a[2]), "r"(a[3]), "r"(b0), "r"(b1));
}
__device__ __forceinline__ void ldsm_x4(uint32_t r[4], uint32_t addr)
{
    asm volatile("ldmatrix.sync.aligned.m8n8.x4.shared.b16 {%0,%1,%2,%3}, [%4];"
        : "=r"(r[0]), "=r"(r[1]), "=r"(r[2]), "=r"(r[3]) : "r"(addr));
}
__device__ __forceinline__ void cp_async16(uint32_t saddr, const void* g)
{
    asm volatile("cp.async.cg.shared.global [%0], [%1], 16;" :: "r"(saddr), "l"(g));
}
// L1-cached variant for weight (B) operands: heavy cross-block reuse per SM.
__device__ __forceinline__ void cp_async16_ca(uint32_t saddr, const void* g)
{
    asm volatile("cp.async.ca.shared.global [%0], [%1], 16;" :: "r"(saddr), "l"(g));
}
__device__ __forceinline__ void cp_commit()
{
    asm volatile("cp.async.commit_group;");
}
template<int N> __device__ __forceinline__ void cp_wait()
{
    asm volatile("cp.async.wait_group %0;" :: "n"(N));
}
__device__ __forceinline__ uint32_t smem_u32(const void* p)
{
    uint32_t a;
    asm("{ .reg .u64 t; cvta.to.shared.u64 t, %1; cvt.u32.u64 %0, t; }"
        : "=r"(a) : "l"(p));
    return a;
}

// ---------------------------------------------------------------------------
// 128x128 warp-MMA GEMM (8 warps, warp tile 64x32), 3-stage cp.async.
// issue(c+2) BEFORE wait — keeps cp.async off the critical path (R9 lesson).
// acc[fm][fn][i]: m = wm+fm*16+g+8*(i>>1), n = wn+fn*8+tq*2+(i&1)
// ---------------------------------------------------------------------------
__device__ __forceinline__ void wgemm(
    const __nv_bfloat16* __restrict__ A, int lda,
    const __nv_bfloat16* __restrict__ B, int ldb,
    int m0, int n0, int nchunks, uint32_t sbase,
    float (&acc)[4][4][4])
{
    const int tid  = threadIdx.x;
    const int lane = tid & 31;
    const int w    = tid >> 5;
    const int wm   = (w & 1) * 64;
    const int wn   = (w >> 1) * 32;
    const int r_ld = tid >> 3;
    const int cc_ld = tid & 7;

    const int a_row = (lane & 7) + ((lane >> 3) & 1) * 8;
    const int a_k16 = ((lane >> 4) & 1) * 16;
    const int b_row = (lane & 7) + ((lane >> 4) & 1) * 8;
    const int b_k16 = ((lane >> 3) & 1) * 16;

    #pragma unroll
    for (int fm = 0; fm < 4; fm++)
        #pragma unroll
        for (int fn = 0; fn < 4; fn++)
            #pragma unroll
            for (int i = 0; i < 4; i++) acc[fm][fn][i] = 0.f;

    auto issue = [&](int c) {
        int s = c % 3;
        int k0 = c << 6;
        uint32_t base = sbase + s * 32768;
        uint32_t off = SMEM_SWIZZLE_128B((uint32_t)(r_ld * 128 + cc_ld * 16));
        #pragma unroll
        for (int it = 0; it < 4; it++) {
            int r = it * 32 + r_ld;
            cp_async16(base + it * 4096 + off,
                       A + (size_t)(m0 + r) * lda + k0 + cc_ld * 8);
            cp_async16_ca(base + 16384 + it * 4096 + off,
                          B + (size_t)(n0 + r) * ldb + k0 + cc_ld * 8);
        }
        cp_commit();
    };

    issue(0);
    if (nchunks > 1) issue(1);

    for (int c = 0; c < nchunks; c++) {
        if (c + 2 < nchunks) { issue(c + 2); cp_wait<2>(); }
        else if (c + 1 < nchunks) cp_wait<1>();
        else cp_wait<0>();
        __syncthreads();

        uint32_t Ab = sbase + (c % 3) * 32768;
        uint32_t Bb = Ab + 16384;
        #pragma unroll
        for (int ks = 0; ks < 4; ks++) {
            int kb = ks * 32;
            uint32_t a[4][4];
            #pragma unroll
            for (int fm = 0; fm < 4; fm++) {
                int r = wm + fm * 16 + a_row;
                ldsm_x4(a[fm], Ab + SMEM_SWIZZLE_128B((uint32_t)(r * 128 + kb + a_k16)));
            }
            uint32_t bfr[2][4];
            #pragma unroll
            for (int fp = 0; fp < 2; fp++) {
                int rn = wn + fp * 16 + b_row;
                ldsm_x4(bfr[fp], Bb + SMEM_SWIZZLE_128B((uint32_t)(rn * 128 + kb + b_k16)));
            }
            #pragma unroll
            for (int fn = 0; fn < 4; fn++) {
                uint32_t b0 = bfr[fn >> 1][(fn & 1) * 2];
                uint32_t b1 = bfr[fn >> 1][(fn & 1) * 2 + 1];
                #pragma unroll
                for (int fm = 0; fm < 4; fm++)
                    mma16816(acc[fm][fn], a[fm], b0, b1);
            }
        }
        __syncthreads();
    }
}

// ---------------------------------------------------------------------------
// LN1
// ---------------------------------------------------------------------------
__global__ __launch_bounds__(256) void ln1_kernel(
    const float* __restrict__ x,
    const float* __restrict__ gam,
    const float* __restrict__ bet)
{
    __shared__ float sm[256][33];
    __shared__ float psum[8][32], psq[8][32];
    __shared__ float mu[32], rs[32];

    int bf  = blockIdx.y;
    int hw0 = blockIdx.x * 32;
    int tid = threadIdx.x;
    int tx  = tid & 31, ty = tid >> 5;

    const float* xp = x + (size_t)bf * 256 * HWS;
    #pragma unroll
    for (int c0 = 0; c0 < 256; c0 += 8) {
        int c = c0 + ty;
        sm[c][tx] = xp[(size_t)c * HWS + hw0 + tx];
    }
    __syncthreads();

    float s = 0.f, sq = 0.f;
    #pragma unroll
    for (int k = 0; k < 32; k++) {
        float v = sm[ty * 32 + k][tx];
        s += v; sq += v * v;
    }
    psum[ty][tx] = s; psq[ty][tx] = sq;
    __syncthreads();

    if (ty == 0) {
        float S = 0.f, Q = 0.f;
        #pragma unroll
        for (int k = 0; k < 8; k++) { S += psum[k][tx]; Q += psq[k][tx]; }
        float m   = S * (1.f / 256.f);
        float var = Q * (1.f / 256.f) - m * m;
        mu[tx] = m;
        rs[tx] = rsqrtf(var + 1e-5f);
    }
    __syncthreads();

    int tokl = tid >> 3, cg = tid & 7;
    int tok  = bf * HWS + hw0 + tokl;
    float m = mu[tokl], r = rs[tokl];
    size_t rowoff = (size_t)tok * 256;
    #pragma unroll
    for (int k = 0; k < 32; k++) {
        int c = k * 8 + cg;
        float v = sm[c][tokl];
        g_xn_bf[rowoff + c] = __float2bfloat16_rn((v - m) * r * gam[c] + bet[c]);
    }
}

// ---------------------------------------------------------------------------
__global__ __launch_bounds__(256) void cvt_all(
    const float* __restrict__ wh, const float* __restrict__ wv,
    const float* __restrict__ wf, const float* __restrict__ w1,
    const float* __restrict__ w2)
{
    int i = blockIdx.x * 256 + threadIdx.x;
    if (i < 49152)        g_wh[i]          = __float2bfloat16_rn(wh[i]);
    else if (i < 98304)   g_wv[i - 49152]  = __float2bfloat16_rn(wv[i - 49152]);
    else if (i < 163840)  g_wf[i - 98304]  = __float2bfloat16_rn(wf[i - 98304]);
    else if (i < 425984)  g_w1[i - 163840] = __float2bfloat16_rn(w1[i - 163840]);
    else if (i < 688128)  g_w2[i - 425984] = __float2bfloat16_rn(w2[i - 425984]);
}

// ---------------------------------------------------------------------------
// QKV GEMM -> token-major g_qkv_bf[branch][t][384]
// ---------------------------------------------------------------------------
__global__ __launch_bounds__(256, 2) void qkv_mm(
    const float* __restrict__ bh, const float* __restrict__ bv)
{
    extern __shared__ __align__(1024) char dsm[];
    uint32_t sbase = smem_u32(dsm);
    int branch = blockIdx.z;
    int m0 = blockIdx.y * 128, n0 = blockIdx.x * 128;
    const __nv_bfloat16* A = g_xn_bf + branch * 128;
    const __nv_bfloat16* W = branch ? g_wv : g_wh;
    const float* bias = branch ? bv : bh;

    float acc[4][4][4];
    wgemm(A, 256, W, 128, m0, n0, 2, sbase, acc);

    const int lane = threadIdx.x & 31, w = threadIdx.x >> 5;
    const int wm = (w & 1) * 64, wn = (w >> 1) * 32;
    const int g = lane >> 2, tq = lane & 3;
    #pragma unroll
    for (int fm = 0; fm < 4; fm++)
        #pragma unroll
        for (int i2 = 0; i2 < 2; i2++) {
            int ml = wm + fm * 16 + g + i2 * 8;
            #pragma unroll
            for (int fn = 0; fn < 4; fn++) {
                int ol = wn + fn * 8 + tq * 2;
                int o  = n0 + ol;
                float v0 = acc[fm][fn][i2 * 2]     + __ldg(bias + o);
                float v1 = acc[fm][fn][i2 * 2 + 1] + __ldg(bias + o + 1);
                __nv_bfloat162 p = __floats2bfloat162_rn(v0, v1);
                *(uint32_t*)(dsm + ml * 272 + ol * 2) = *(uint32_t*)&p;
            }
        }
    __syncthreads();

    int row = threadIdx.x >> 1, half = threadIdx.x & 1;
    size_t t = (size_t)m0 + row;
    __nv_bfloat16* dst = g_qkv_bf + (size_t)branch * QKV_HALF + t * 384 + n0 + half * 64;
    const char* src = dsm + row * 272 + half * 128;
    #pragma unroll
    for (int j = 0; j < 8; j++)
        *(uint4*)(dst + j * 8) = *(const uint4*)(src + j * 16);
}

// ---------------------------------------------------------------------------
// Attention
// ---------------------------------------------------------------------------
__global__ __launch_bounds__(256) void attn_kernel()
{
    int id   = blockIdx.x;
    int dir  = id >> 10;
    int b    = (id >> 9) & 1;
    int n    = (id >> 6) & 7;
    int l    = id & 63;

    int tid = threadIdx.x;
    int dd  = tid >> 2;
    int dq  = (tid & 3) * 4;

    const __nv_bfloat16* buf = g_qkv_bf + (size_t)dir * QKV_HALF;
    int hw = dir ? dd * 64 + l : l * 64 + dd;
    int oq = n * 16 + dq;

    float4 q[5], k[5];
    #pragma unroll
    for (int i = 0; i < 5; i++) {
        size_t t = ((size_t)(b * 5 + i) * 4096 + hw) * 384;
        uint2 rq = *reinterpret_cast<const uint2*>(buf + t + oq);
        uint2 rk = *reinterpret_cast<const uint2*>(buf + t + 128 + oq);
        float2 q0 = __bfloat1622float2(*reinterpret_cast<__nv_bfloat162*>(&rq.x));
        float2 q1 = __bfloat1622float2(*reinterpret_cast<__nv_bfloat162*>(&rq.y));
        float2 k0 = __bfloat1622float2(*reinterpret_cast<__nv_bfloat162*>(&rk.x));
        float2 k1 = __bfloat1622float2(*reinterpret_cast<__nv_bfloat162*>(&rk.y));
        q[i] = make_float4(q0.x, q0.y, q1.x, q1.y);
        k[i] = make_float4(k0.x, k0.y, k1.x, k1.y);
    }
    float p[25];
    #pragma unroll
    for (int i = 0; i < 5; i++)
        #pragma unroll
        for (int j = 0; j < 5; j++) {
            float4 a = q[i], c = k[j];
            p[i*5+j] = a.x*c.x + a.y*c.y + a.z*c.z + a.w*c.w;
        }

    __shared__ float red[25][8];
    #pragma unroll
    for (int e = 0; e < 25; e++) {
        float v = p[e];
        #pragma unroll
        for (int off = 16; off; off >>= 1) v += __shfl_down_sync(0xffffffffu, v, off);
        if ((tid & 31) == 0) red[e][tid >> 5] = v;
    }
    __syncthreads();

    __shared__ float P[5][5];
    if (tid < 5) {
        float srow[5];
        float mx = -1e30f;
        #pragma unroll
        for (int j = 0; j < 5; j++) {
            float s = 0.f;
            #pragma unroll
            for (int wdx = 0; wdx < 8; wdx++) s += red[tid*5+j][wdx];
            s *= (1.f / 32.f);
            srow[j] = s; mx = fmaxf(mx, s);
        }
        float se = 0.f;
        #pragma unroll
        for (int j = 0; j < 5; j++) { srow[j] = __expf(srow[j] - mx); se += srow[j]; }
        float inv = 1.f / se;
        #pragma unroll
        for (int j = 0; j < 5; j++) P[tid][j] = srow[j] * inv;
    }
    __syncthreads();

    float4 o[5];
    #pragma unroll
    for (int i = 0; i < 5; i++) o[i] = make_float4(0.f, 0.f, 0.f, 0.f);
    #pragma unroll
    for (int j = 0; j < 5; j++) {
        size_t t = ((size_t)(b * 5 + j) * 4096 + hw) * 384;
        uint2 rv = *reinterpret_cast<const uint2*>(buf + t + 256 + oq);
        float2 v0 = __bfloat1622float2(*reinterpret_cast<__nv_bfloat162*>(&rv.x));
        float2 v1 = __bfloat1622float2(*reinterpret_cast<__nv_bfloat162*>(&rv.y));
        #pragma unroll
        for (int i = 0; i < 5; i++) {
            float pij = P[i][j];
            o[i].x = fmaf(pij, v0.x, o[i].x);
            o[i].y = fmaf(pij, v0.y, o[i].y);
            o[i].z = fmaf(pij, v1.x, o[i].z);
            o[i].w = fmaf(pij, v1.y, o[i].w);
        }
    }

    int c = dir ? (128 + n * 16 + dq) : (n * 16 + dq);
    #pragma unroll
    for (int fi = 0; fi < 5; fi++) {
        size_t tok = (size_t)(b * 5 + fi) * 4096 + hw;
        __nv_bfloat162 lo = __floats2bfloat162_rn(o[fi].x, o[fi].y);
        __nv_bfloat162 hi = __floats2bfloat162_rn(o[fi].z, o[fi].w);
        uint2 packed;
        packed.x = *reinterpret_cast<uint32_t*>(&lo);
        packed.y = *reinterpret_cast<uint32_t*>(&hi);
        *reinterpret_cast<uint2*>(g_ao_bf + tok * 256 + c) = packed;
    }
}

// ---------------------------------------------------------------------------
// Output projection + residual: y = ao @ wf^T + bf + x (fp32, channel-major)
// Residual read directly from x (B,F,C,H,W): coalesced along hw.
// ---------------------------------------------------------------------------
__global__ __launch_bounds__(256, 2) void proj_mm(
    const float* __restrict__ x, const float* __restrict__ bfp)
{
    extern __shared__ __align__(1024) char dsm[];
    uint32_t sbase = smem_u32(dsm);
    int m0 = blockIdx.y * 128, n0 = blockIdx.x * 128;
    int bfi = m0 >> 12, hw0 = m0 & 4095;

    float acc[4][4][4];
    wgemm(g_ao_bf, 256, g_wf, 256, m0, n0, 4, sbase, acc);

    // stage residual from x, channel-major: Rs[c][m], stride 132 floats
    float* Rs = reinterpret_cast<float*>(dsm);
    {
        int tid = threadIdx.x;
        #pragma unroll
        for (int it = 0; it < 16; it++) {
            int idx = it * 256 + tid;
            int c = idx >> 5, hw4 = idx & 31;
            float4 v = *reinterpret_cast<const float4*>(
                x + ((size_t)bfi * 256 + n0 + c) * 4096 + hw0 + hw4 * 4);
            *reinterpret_cast<float4*>(Rs + c * 132 + hw4 * 4) = v;
        }
    }
    __syncthreads();

    const int lane = threadIdx.x & 31, w = threadIdx.x >> 5;
    const int wm = (w & 1) * 64, wn = (w >> 1) * 32;
    const int g = lane >> 2, tq = lane & 3;
    #pragma unroll
    for (int fm = 0; fm < 4; fm++)
        #pragma unroll
        for (int fn = 0; fn < 4; fn++) {
            int ol = wn + fn * 8 + tq * 2;
            float b0 = __ldg(bfp + n0 + ol), b1 = __ldg(bfp + n0 + ol + 1);
            #pragma unroll
            for (int i2 = 0; i2 < 2; i2++) {
                int ml = wm + fm * 16 + g + i2 * 8;
                Rs[ol * 132 + ml]       += acc[fm][fn][i2*2]   + b0;
                Rs[(ol + 1) * 132 + ml] += acc[fm][fn][i2*2+1] + b1;
            }
        }
    __syncthreads();

    // write y channel-major (coalesced along hw)
    {
        int tid = threadIdx.x;
        #pragma unroll
        for (int it = 0; it < 16; it++) {
            int idx = it * 256 + tid;
            int c = idx >> 5, hw4 = idx & 31;
            float4 v = *reinterpret_cast<const float4*>(Rs + c * 132 + hw4 * 4);
            *reinterpret_cast<float4*>(
                g_yT + ((size_t)bfi * 256 + n0 + c) * 4096 + hw0 + hw4 * 4) = v;
        }
    }
}

// ---------------------------------------------------------------------------
// LN2: g_yT (channel-major fp32) -> g_tn_bf (token-major bf16).
// Block: 256 threads = 32 tokens x 8 channel-groups, transpose in smem.
// ---------------------------------------------------------------------------
__global__ __launch_bounds__(256) void ln2_kernel(
    const float* __restrict__ gam, const float* __restrict__ bet)
{
    __shared__ float sm[256][33];
    __shared__ float psum[8][32], psq[8][32];
    __shared__ float mu[32], rs[32];

    int bf  = blockIdx.y;
    int hw0 = blockIdx.x * 32;
    int tid = threadIdx.x;
    int tx  = tid & 31, ty = tid >> 5;

    const float* yp = g_yT + (size_t)bf * 256 * HWS;
    #pragma unroll
    for (int c0 = 0; c0 < 256; c0 += 8) {
        int c = c0 + ty;
        sm[c][tx] = yp[(size_t)c * HWS + hw0 + tx];
    }
    __syncthreads();

    float s = 0.f, sq = 0.f;
    #pragma unroll
    for (int k = 0; k < 32; k++) {
        float v = sm[ty * 32 + k][tx];
        s += v; sq += v * v;
    }
    psum[ty][tx] = s; psq[ty][tx] = sq;
    __syncthreads();

    if (ty == 0) {
        float S = 0.f, Q = 0.f;
        #pragma unroll
        for (int k = 0; k < 8; k++) { S += psum[k][tx]; Q += psq[k][tx]; }
        float m   = S * (1.f / 256.f);
        float var = Q * (1.f / 256.f) - m * m;
        mu[tx] = m;
        rs[tx] = rsqrtf(var + 1e-5f);
    }
    __syncthreads();

    int tokl = tid >> 3, cg = tid & 7;
    int tok  = bf * HWS + hw0 + tokl;
    float m = mu[tokl], r = rs[tokl];
    size_t rowoff = (size_t)tok * 256;
    #pragma unroll
    for (int k = 0; k < 32; k++) {
        int c = k * 8 + cg;
        float v = sm[c][tokl];
        g_tn_bf[rowoff + c] = __float2bfloat16_rn((v - m) * r * gam[c] + bet[c]);
    }
}

// ---------------------------------------------------------------------------
// MLP GEMM1 + exact GELU -> g_hid_bf (bf16 token-major)
// ---------------------------------------------------------------------------
__global__ __launch_bounds__(256, 2) void mlp1_mm(const float* __restrict__ b1)
{
    extern __shared__ __align__(1024) char dsm[];
    uint32_t sbase = smem_u32(dsm);
    int m0 = blockIdx.y * 128, n0 = blockIdx.x * 128;

    float acc[4][4][4];
    wgemm(g_tn_bf, 256, g_w1, 256, m0, n0, 4, sbase, acc);

    const int lane = threadIdx.x & 31, w = threadIdx.x >> 5;
    const int wm = (w & 1) * 64, wn = (w >> 1) * 32;
    const int g = lane >> 2, tq = lane & 3;
    #pragma unroll
    for (int fm = 0; fm < 4; fm++)
        #pragma unroll
        for (int i2 = 0; i2 < 2; i2++) {
            int ml = wm + fm * 16 + g + i2 * 8;
            #pragma unroll
            for (int fn = 0; fn < 4; fn++) {
                int ol = wn + fn * 8 + tq * 2;
                int o  = n0 + ol;
                float h0 = acc[fm][fn][i2 * 2]     + __ldg(b1 + o);
                float h1 = acc[fm][fn][i2 * 2 + 1] + __ldg(b1 + o + 1);
                float gl0 = 0.5f * h0 * (1.f + erff(h0 * 0.70710678118654752f));
                float gl1 = 0.5f * h1 * (1.f + erff(h1 * 0.70710678118654752f));
                __nv_bfloat162 p = __floats2bfloat162_rn(gl0, gl1);
                *(uint32_t*)(dsm + ml * 272 + ol * 2) = *(uint32_t*)&p;
            }
        }
    __syncthreads();

    int row = threadIdx.x >> 1, half = threadIdx.x & 1;
    __nv_bfloat16* dst = g_hid_bf + (size_t)(m0 + row) * 1024 + n0 + half * 64;
    const char* src = dsm + row * 272 + half * 128;
    #pragma unroll
    for (int j = 0; j < 8; j++)
        *(uint4*)(dst + j * 8) = *(const uint4*)(src + j * 16);
}

// ---------------------------------------------------------------------------
// MLP GEMM2 + residual (g_yT) + channel-major store to out (B,F,C,H,W)
// ---------------------------------------------------------------------------
__global__ __launch_bounds__(256, 2) void mlp2_mm(
    const float* __restrict__ b2, float* __restrict__ out)
{
    extern __shared__ __align__(1024) char dsm[];
    uint32_t sbase = smem_u32(dsm);
    int m0 = blockIdx.y * 128, n0 = blockIdx.x * 128;
    int bfi = m0 >> 12, hw0 = m0 & 4095;

    float acc[4][4][4];
    wgemm(g_hid_bf, 1024, g_w2, 1024, m0, n0, 16, sbase, acc);

    // stage y residual channel-major: Rs[c][m], stride 132
    float* Rs = reinterpret_cast<float*>(dsm);
    {
        int tid = threadIdx.x;
        #pragma unroll
        for (int it = 0; it < 16; it++) {
            int idx = it * 256 + tid;
            int c = idx >> 5, hw4 = idx & 31;
            float4 v = *reinterpret_cast<const float4*>(
                g_yT + ((size_t)bfi * 256 + n0 + c) * 4096 + hw0 + hw4 * 4);
            *reinterpret_cast<float4*>(Rs + c * 132 + hw4 * 4) = v;
        }
    }
    __syncthreads();

    const int lane = threadIdx.x & 31, w = threadIdx.x >> 5;
    const int wm = (w & 1) * 64, wn = (w >> 1) * 32;
    const int g = lane >> 2, tq = lane & 3;
    #pragma unroll
    for (int fm = 0; fm < 4; fm++)
        #pragma unroll
        for (int fn = 0; fn < 4; fn++) {
            int ol = wn + fn * 8 + tq * 2;
            float b0 = __ldg(b2 + n0 + ol), b1 = __ldg(b2 + n0 + ol + 1);
            #pragma unroll
            for (int i2 = 0; i2 < 2; i2++) {
                int ml = wm + fm * 16 + g + i2 * 8;
                Rs[ol * 132 + ml]       += acc[fm][fn][i2*2]   + b0;
                Rs[(ol + 1) * 132 + ml] += acc[fm][fn][i2*2+1] + b1;
            }
        }
    __syncthreads();

    {
        int tid = threadIdx.x;
        #pragma unroll
        for (int it = 0; it < 16; it++) {
            int idx = it * 256 + tid;
            int c = idx >> 5, hw4 = idx & 31;
            float4 v = *reinterpret_cast<const float4*>(Rs + c * 132 + hw4 * 4);
            *reinterpret_cast<float4*>(
                out + ((size_t)bfi * 256 + n0 + c) * 4096 + hw0 + hw4 * 4) = v;
        }
    }
}

// ---------------------------------------------------------------------------
extern "C" void kernel_launch(void* const* d_in, const int* in_sizes, int n_in,
                              void* d_out, int out_size)
{
    const float* x     = (const float*)d_in[0];
    const float* ln1_g = (const float*)d_in[1];
    const float* ln1_b = (const float*)d_in[2];
    const float* wh    = (const float*)d_in[3];
    const float* bh    = (const float*)d_in[4];
    const float* wv    = (const float*)d_in[5];
    const float* bv    = (const float*)d_in[6];
    const float* wf    = (const float*)d_in[7];
    const float* bf    = (const float*)d_in[8];
    const float* ln2_g = (const float*)d_in[9];
    const float* ln2_b = (const float*)d_in[10];
    const float* w1    = (const float*)d_in[11];
    const float* b1    = (const float*)d_in[12];
    const float* w2    = (const float*)d_in[13];
    const float* b2    = (const float*)d_in[14];
    float* out = (float*)d_out;

    cudaFuncSetAttribute(qkv_mm,  cudaFuncAttributeMaxDynamicSharedMemorySize, SMEM_DYN128);
    cudaFuncSetAttribute(proj_mm, cudaFuncAttributeMaxDynamicSharedMemorySize, SMEM_DYN128);
    cudaFuncSetAttribute(mlp1_mm, cudaFuncAttributeMaxDynamicSharedMemorySize, SMEM_DYN128);
    cudaFuncSetAttribute(mlp2_mm, cudaFuncAttributeMaxDynamicSharedMemorySize, SMEM_DYN128);

    cvt_all<<<2688, 256>>>(wh, wv, wf, w1, w2);
    ln1_kernel<<<dim3(128, 10), 256>>>(x, ln1_g, ln1_b);
    qkv_mm    <<<dim3(3, 320, 2), 256, SMEM_DYN128>>>(bh, bv);
    attn_kernel<<<2048, 256>>>();
    proj_mm   <<<dim3(2, 320), 256, SMEM_DYN128>>>(x, bf);
    ln2_kernel<<<dim3(128, 10), 256>>>(ln2_g, ln2_b);
    mlp1_mm   <<<dim3(8, 320), 256, SMEM_DYN128>>>(b1);
    mlp2_mm   <<<dim3(2, 320), 256, SMEM_DYN128>>>(b2, out);
}

// round 15
// speedup vs baseline: 1.0418x; 1.0010x over previous
#include <cuda_runtime.h>
#include <cuda_bf16.h>
#include <math.h>
#include <cstdint>

#define HWS  4096
#define TOK  40960
#define QKV_HALF (TOK*384)

// ---------------------------------------------------------------------------
// Static device scratch
// ---------------------------------------------------------------------------
__device__ __nv_bfloat16 g_xn_bf [TOK*256];    // LN1 out (bf16, token-major)
__device__ __nv_bfloat16 g_qkv_bf[2*QKV_HALF]; // qkv token-major [branch][t][384]
__device__ __nv_bfloat16 g_ao_bf [TOK*256];    // attention out (bf16 token-major)
__device__ float         g_yT    [TOK*256];    // y channel-major [bf][c][hw] fp32
__device__ __nv_bfloat16 g_tn_bf [TOK*256];    // LN2 out (bf16 token-major)
__device__ __nv_bfloat16 g_hid_bf[TOK*1024];   // MLP hidden (bf16)
__device__ __nv_bfloat16 g_wh[384*128];
__device__ __nv_bfloat16 g_wv[384*128];
__device__ __nv_bfloat16 g_wf[256*256];
__device__ __nv_bfloat16 g_w1[1024*256];
__device__ __nv_bfloat16 g_w2[256*1024];

#define SMEM_SWIZZLE_128B(byte_offset) \
    ((byte_offset) ^ (((byte_offset) >> 3) & 0x70))

#define SMEM_DYN128 98304     // 3 stages x (16KB A + 16KB B)

// ---------------------------------------------------------------------------
// Baseline-ISA building blocks
// ---------------------------------------------------------------------------
__device__ __forceinline__ void mma16816(float d[4], const uint32_t a[4],
                                         uint32_t b0, uint32_t b1)
{
    asm volatile(
        "mma.sync.aligned.m16n8k16.row.col.f32.bf16.bf16.f32 "
        "{%0,%1,%2,%3},{%4,%5,%6,%7},{%8,%9},{%0,%1,%2,%3};"
        : "+f"(d[0]), "+f"(d[1]), "+f"(d[2]), "+f"(d[3])
        : "r"(a[0]), "r"(a[1]), "r"(a[2]), "r"(a[3]), "r"(b0), "r"(b1));
}
__device__ __forceinline__ void ldsm_x4(uint32_t r[4], uint32_t addr)
{
    asm volatile("ldmatrix.sync.aligned.m8n8.x4.shared.b16 {%0,%1,%2,%3}, [%4];"
        : "=r"(r[0]), "=r"(r[1]), "=r"(r[2]), "=r"(r[3]) : "r"(addr));
}
__device__ __forceinline__ void cp_async16(uint32_t saddr, const void* g)
{
    asm volatile("cp.async.cg.shared.global [%0], [%1], 16;" :: "r"(saddr), "l"(g));
}
// L1-cached variant for weight (B) operands: heavy cross-block reuse per SM.
__device__ __forceinline__ void cp_async16_ca(uint32_t saddr, const void* g)
{
    asm volatile("cp.async.ca.shared.global [%0], [%1], 16;" :: "r"(saddr), "l"(g));
}
__device__ __forceinline__ void cp_commit()
{
    asm volatile("cp.async.commit_group;");
}
template<int N> __device__ __forceinline__ void cp_wait()
{
    asm volatile("cp.async.wait_group %0;" :: "n"(N));
}
__device__ __forceinline__ uint32_t smem_u32(const void* p)
{
    uint32_t a;
    asm("{ .reg .u64 t; cvta.to.shared.u64 t, %1; cvt.u32.u64 %0, t; }"
        : "=r"(a) : "l"(p));
    return a;
}

// ---------------------------------------------------------------------------
// 128x128 warp-MMA GEMM (8 warps, warp tile 64x32), 3-stage cp.async.
// ---------------------------------------------------------------------------
__device__ __forceinline__ void wgemm(
    const __nv_bfloat16* __restrict__ A, int lda,
    const __nv_bfloat16* __restrict__ B, int ldb,
    int m0, int n0, int nchunks, uint32_t sbase,
    float (&acc)[4][4][4])
{
    const int tid  = threadIdx.x;
    const int lane = tid & 31;
    const int w    = tid >> 5;
    const int wm   = (w & 1) * 64;
    const int wn   = (w >> 1) * 32;
    const int r_ld = tid >> 3;
    const int cc_ld = tid & 7;

    const int a_row = (lane & 7) + ((lane >> 3) & 1) * 8;
    const int a_k16 = ((lane >> 4) & 1) * 16;
    const int b_row = (lane & 7) + ((lane >> 4) & 1) * 8;
    const int b_k16 = ((lane >> 3) & 1) * 16;

    #pragma unroll
    for (int fm = 0; fm < 4; fm++)
        #pragma unroll
        for (int fn = 0; fn < 4; fn++)
            #pragma unroll
            for (int i = 0; i < 4; i++) acc[fm][fn][i] = 0.f;

    auto issue = [&](int c) {
        int s = c % 3;
        int k0 = c << 6;
        uint32_t base = sbase + s * 32768;
        uint32_t off = SMEM_SWIZZLE_128B((uint32_t)(r_ld * 128 + cc_ld * 16));
        #pragma unroll
        for (int it = 0; it < 4; it++) {
            int r = it * 32 + r_ld;
            cp_async16(base + it * 4096 + off,
                       A + (size_t)(m0 + r) * lda + k0 + cc_ld * 8);
            cp_async16_ca(base + 16384 + it * 4096 + off,
                          B + (size_t)(n0 + r) * ldb + k0 + cc_ld * 8);
        }
        cp_commit();
    };

    issue(0);
    if (nchunks > 1) issue(1);

    for (int c = 0; c < nchunks; c++) {
        if (c + 2 < nchunks) { issue(c + 2); cp_wait<2>(); }
        else if (c + 1 < nchunks) cp_wait<1>();
        else cp_wait<0>();
        __syncthreads();

        uint32_t Ab = sbase + (c % 3) * 32768;
        uint32_t Bb = Ab + 16384;
        #pragma unroll
        for (int ks = 0; ks < 4; ks++) {
            int kb = ks * 32;
            uint32_t a[4][4];
            #pragma unroll
            for (int fm = 0; fm < 4; fm++) {
                int r = wm + fm * 16 + a_row;
                ldsm_x4(a[fm], Ab + SMEM_SWIZZLE_128B((uint32_t)(r * 128 + kb + a_k16)));
            }
            uint32_t bfr[2][4];
            #pragma unroll
            for (int fp = 0; fp < 2; fp++) {
                int rn = wn + fp * 16 + b_row;
                ldsm_x4(bfr[fp], Bb + SMEM_SWIZZLE_128B((uint32_t)(rn * 128 + kb + b_k16)));
            }
            #pragma unroll
            for (int fn = 0; fn < 4; fn++) {
                uint32_t b0 = bfr[fn >> 1][(fn & 1) * 2];
                uint32_t b1 = bfr[fn >> 1][(fn & 1) * 2 + 1];
                #pragma unroll
                for (int fm = 0; fm < 4; fm++)
                    mma16816(acc[fm][fn], a[fm], b0, b1);
            }
        }
        __syncthreads();
    }
}

// ---------------------------------------------------------------------------
// LN1
// ---------------------------------------------------------------------------
__global__ __launch_bounds__(256) void ln1_kernel(
    const float* __restrict__ x,
    const float* __restrict__ gam,
    const float* __restrict__ bet)
{
    __shared__ float sm[256][33];
    __shared__ float psum[8][32], psq[8][32];
    __shared__ float mu[32], rs[32];

    int bf  = blockIdx.y;
    int hw0 = blockIdx.x * 32;
    int tid = threadIdx.x;
    int tx  = tid & 31, ty = tid >> 5;

    const float* xp = x + (size_t)bf * 256 * HWS;
    #pragma unroll
    for (int c0 = 0; c0 < 256; c0 += 8) {
        int c = c0 + ty;
        sm[c][tx] = xp[(size_t)c * HWS + hw0 + tx];
    }
    __syncthreads();

    float s = 0.f, sq = 0.f;
    #pragma unroll
    for (int k = 0; k < 32; k++) {
        float v = sm[ty * 32 + k][tx];
        s += v; sq += v * v;
    }
    psum[ty][tx] = s; psq[ty][tx] = sq;
    __syncthreads();

    if (ty == 0) {
        float S = 0.f, Q = 0.f;
        #pragma unroll
        for (int k = 0; k < 8; k++) { S += psum[k][tx]; Q += psq[k][tx]; }
        float m   = S * (1.f / 256.f);
        float var = Q * (1.f / 256.f) - m * m;
        mu[tx] = m;
        rs[tx] = rsqrtf(var + 1e-5f);
    }
    __syncthreads();

    int tokl = tid >> 3, cg = tid & 7;
    int tok  = bf * HWS + hw0 + tokl;
    float m = mu[tokl], r = rs[tokl];
    size_t rowoff = (size_t)tok * 256;
    #pragma unroll
    for (int k = 0; k < 32; k++) {
        int c = k * 8 + cg;
        float v = sm[c][tokl];
        g_xn_bf[rowoff + c] = __float2bfloat16_rn((v - m) * r * gam[c] + bet[c]);
    }
}

// ---------------------------------------------------------------------------
__global__ __launch_bounds__(256) void cvt_all(
    const float* __restrict__ wh, const float* __restrict__ wv,
    const float* __restrict__ wf, const float* __restrict__ w1,
    const float* __restrict__ w2)
{
    int i = blockIdx.x * 256 + threadIdx.x;
    if (i < 49152)        g_wh[i]          = __float2bfloat16_rn(wh[i]);
    else if (i < 98304)   g_wv[i - 49152]  = __float2bfloat16_rn(wv[i - 49152]);
    else if (i < 163840)  g_wf[i - 98304]  = __float2bfloat16_rn(wf[i - 98304]);
    else if (i < 425984)  g_w1[i - 163840] = __float2bfloat16_rn(w1[i - 163840]);
    else if (i < 688128)  g_w2[i - 425984] = __float2bfloat16_rn(w2[i - 425984]);
}

// ---------------------------------------------------------------------------
// QKV GEMM -> token-major g_qkv_bf[branch][t][384]
// ---------------------------------------------------------------------------
__global__ __launch_bounds__(256, 2) void qkv_mm(
    const float* __restrict__ bh, const float* __restrict__ bv)
{
    extern __shared__ __align__(1024) char dsm[];
    uint32_t sbase = smem_u32(dsm);
    int branch = blockIdx.z;
    int m0 = blockIdx.y * 128, n0 = blockIdx.x * 128;
    const __nv_bfloat16* A = g_xn_bf + branch * 128;
    const __nv_bfloat16* W = branch ? g_wv : g_wh;
    const float* bias = branch ? bv : bh;

    float acc[4][4][4];
    wgemm(A, 256, W, 128, m0, n0, 2, sbase, acc);

    const int lane = threadIdx.x & 31, w = threadIdx.x >> 5;
    const int wm = (w & 1) * 64, wn = (w >> 1) * 32;
    const int g = lane >> 2, tq = lane & 3;
    #pragma unroll
    for (int fm = 0; fm < 4; fm++)
        #pragma unroll
        for (int i2 = 0; i2 < 2; i2++) {
            int ml = wm + fm * 16 + g + i2 * 8;
            #pragma unroll
            for (int fn = 0; fn < 4; fn++) {
                int ol = wn + fn * 8 + tq * 2;
                int o  = n0 + ol;
                float v0 = acc[fm][fn][i2 * 2]     + __ldg(bias + o);
                float v1 = acc[fm][fn][i2 * 2 + 1] + __ldg(bias + o + 1);
                __nv_bfloat162 p = __floats2bfloat162_rn(v0, v1);
                *(uint32_t*)(dsm + ml * 272 + ol * 2) = *(uint32_t*)&p;
            }
        }
    __syncthreads();

    int row = threadIdx.x >> 1, half = threadIdx.x & 1;
    size_t t = (size_t)m0 + row;
    __nv_bfloat16* dst = g_qkv_bf + (size_t)branch * QKV_HALF + t * 384 + n0 + half * 64;
    const char* src = dsm + row * 272 + half * 128;
    #pragma unroll
    for (int j = 0; j < 8; j++)
        *(uint4*)(dst + j * 8) = *(const uint4*)(src + j * 16);
}

// ---------------------------------------------------------------------------
// Attention: quad-shuffle + smem two-stage reduction (replaces 125-shfl chain)
// ---------------------------------------------------------------------------
__global__ __launch_bounds__(256) void attn_kernel()
{
    int id   = blockIdx.x;
    int dir  = id >> 10;
    int b    = (id >> 9) & 1;
    int n    = (id >> 6) & 7;
    int l    = id & 63;

    int tid = threadIdx.x;
    int dd  = tid >> 2;
    int dq  = (tid & 3) * 4;

    const __nv_bfloat16* buf = g_qkv_bf + (size_t)dir * QKV_HALF;
    int hw = dir ? dd * 64 + l : l * 64 + dd;
    int oq = n * 16 + dq;

    float4 q[5], k[5];
    #pragma unroll
    for (int i = 0; i < 5; i++) {
        size_t t = ((size_t)(b * 5 + i) * 4096 + hw) * 384;
        uint2 rq = *reinterpret_cast<const uint2*>(buf + t + oq);
        uint2 rk = *reinterpret_cast<const uint2*>(buf + t + 128 + oq);
        float2 q0 = __bfloat1622float2(*reinterpret_cast<__nv_bfloat162*>(&rq.x));
        float2 q1 = __bfloat1622float2(*reinterpret_cast<__nv_bfloat162*>(&rq.y));
        float2 k0 = __bfloat1622float2(*reinterpret_cast<__nv_bfloat162*>(&rk.x));
        float2 k1 = __bfloat1622float2(*reinterpret_cast<__nv_bfloat162*>(&rk.y));
        q[i] = make_float4(q0.x, q0.y, q1.x, q1.y);
        k[i] = make_float4(k0.x, k0.y, k1.x, k1.y);
    }
    float p[25];
    #pragma unroll
    for (int i = 0; i < 5; i++)
        #pragma unroll
        for (int j = 0; j < 5; j++) {
            float4 a = q[i], c = k[j];
            p[i*5+j] = a.x*c.x + a.y*c.y + a.z*c.z + a.w*c.w;
        }

    // Stage 1: quad reduce (over dq) — 2 shfls per entry.
    #pragma unroll
    for (int e = 0; e < 25; e++) {
        p[e] += __shfl_xor_sync(0xffffffffu, p[e], 1);
        p[e] += __shfl_xor_sync(0xffffffffu, p[e], 2);
    }
    __shared__ float sq_s[64][26];
    if ((tid & 3) == 0) {
        #pragma unroll
        for (int e = 0; e < 25; e++) sq_s[dd][e] = p[e];
    }
    __syncthreads();

    // Stage 2: 200 threads rebuild red[25][8] (8 dd-partials per entry).
    __shared__ float red[25][8];
    if (tid < 200) {
        int e = tid >> 3, grp = tid & 7;
        float s = 0.f;
        #pragma unroll
        for (int kk = 0; kk < 8; kk++) s += sq_s[grp * 8 + kk][e];
        red[e][grp] = s;
    }
    __syncthreads();

    __shared__ float P[5][5];
    if (tid < 5) {
        float srow[5];
        float mx = -1e30f;
        #pragma unroll
        for (int j = 0; j < 5; j++) {
            float s = 0.f;
            #pragma unroll
            for (int wdx = 0; wdx < 8; wdx++) s += red[tid*5+j][wdx];
            s *= (1.f / 32.f);
            srow[j] = s; mx = fmaxf(mx, s);
        }
        float se = 0.f;
        #pragma unroll
        for (int j = 0; j < 5; j++) { srow[j] = __expf(srow[j] - mx); se += srow[j]; }
        float inv = 1.f / se;
        #pragma unroll
        for (int j = 0; j < 5; j++) P[tid][j] = srow[j] * inv;
    }
    __syncthreads();

    float4 o[5];
    #pragma unroll
    for (int i = 0; i < 5; i++) o[i] = make_float4(0.f, 0.f, 0.f, 0.f);
    #pragma unroll
    for (int j = 0; j < 5; j++) {
        size_t t = ((size_t)(b * 5 + j) * 4096 + hw) * 384;
        uint2 rv = *reinterpret_cast<const uint2*>(buf + t + 256 + oq);
        float2 v0 = __bfloat1622float2(*reinterpret_cast<__nv_bfloat162*>(&rv.x));
        float2 v1 = __bfloat1622float2(*reinterpret_cast<__nv_bfloat162*>(&rv.y));
        #pragma unroll
        for (int i = 0; i < 5; i++) {
            float pij = P[i][j];
            o[i].x = fmaf(pij, v0.x, o[i].x);
            o[i].y = fmaf(pij, v0.y, o[i].y);
            o[i].z = fmaf(pij, v1.x, o[i].z);
            o[i].w = fmaf(pij, v1.y, o[i].w);
        }
    }

    int c = dir ? (128 + n * 16 + dq) : (n * 16 + dq);
    #pragma unroll
    for (int fi = 0; fi < 5; fi++) {
        size_t tok = (size_t)(b * 5 + fi) * 4096 + hw;
        __nv_bfloat162 lo = __floats2bfloat162_rn(o[fi].x, o[fi].y);
        __nv_bfloat162 hi = __floats2bfloat162_rn(o[fi].z, o[fi].w);
        uint2 packed;
        packed.x = *reinterpret_cast<uint32_t*>(&lo);
        packed.y = *reinterpret_cast<uint32_t*>(&hi);
        *reinterpret_cast<uint2*>(g_ao_bf + tok * 256 + c) = packed;
    }
}

// ---------------------------------------------------------------------------
// Output projection + residual: y = ao @ wf^T + bf + x (fp32, channel-major)
// ---------------------------------------------------------------------------
__global__ __launch_bounds__(256, 2) void proj_mm(
    const float* __restrict__ x, const float* __restrict__ bfp)
{
    extern __shared__ __align__(1024) char dsm[];
    uint32_t sbase = smem_u32(dsm);
    int m0 = blockIdx.y * 128, n0 = blockIdx.x * 128;
    int bfi = m0 >> 12, hw0 = m0 & 4095;

    float acc[4][4][4];
    wgemm(g_ao_bf, 256, g_wf, 256, m0, n0, 4, sbase, acc);

    float* Rs = reinterpret_cast<float*>(dsm);
    {
        int tid = threadIdx.x;
        #pragma unroll
        for (int it = 0; it < 16; it++) {
            int idx = it * 256 + tid;
            int c = idx >> 5, hw4 = idx & 31;
            float4 v = *reinterpret_cast<const float4*>(
                x + ((size_t)bfi * 256 + n0 + c) * 4096 + hw0 + hw4 * 4);
            *reinterpret_cast<float4*>(Rs + c * 132 + hw4 * 4) = v;
        }
    }
    __syncthreads();

    const int lane = threadIdx.x & 31, w = threadIdx.x >> 5;
    const int wm = (w & 1) * 64, wn = (w >> 1) * 32;
    const int g = lane >> 2, tq = lane & 3;
    #pragma unroll
    for (int fm = 0; fm < 4; fm++)
        #pragma unroll
        for (int fn = 0; fn < 4; fn++) {
            int ol = wn + fn * 8 + tq * 2;
            float b0 = __ldg(bfp + n0 + ol), b1 = __ldg(bfp + n0 + ol + 1);
            #pragma unroll
            for (int i2 = 0; i2 < 2; i2++) {
                int ml = wm + fm * 16 + g + i2 * 8;
                Rs[ol * 132 + ml]       += acc[fm][fn][i2*2]   + b0;
                Rs[(ol + 1) * 132 + ml] += acc[fm][fn][i2*2+1] + b1;
            }
        }
    __syncthreads();

    {
        int tid = threadIdx.x;
        #pragma unroll
        for (int it = 0; it < 16; it++) {
            int idx = it * 256 + tid;
            int c = idx >> 5, hw4 = idx & 31;
            float4 v = *reinterpret_cast<const float4*>(Rs + c * 132 + hw4 * 4);
            *reinterpret_cast<float4*>(
                g_yT + ((size_t)bfi * 256 + n0 + c) * 4096 + hw0 + hw4 * 4) = v;
        }
    }
}

// ---------------------------------------------------------------------------
// LN2: g_yT (channel-major fp32) -> g_tn_bf (token-major bf16).
// ---------------------------------------------------------------------------
__global__ __launch_bounds__(256) void ln2_kernel(
    const float* __restrict__ gam, const float* __restrict__ bet)
{
    __shared__ float sm[256][33];
    __shared__ float psum[8][32], psq[8][32];
    __shared__ float mu[32], rs[32];

    int bf  = blockIdx.y;
    int hw0 = blockIdx.x * 32;
    int tid = threadIdx.x;
    int tx  = tid & 31, ty = tid >> 5;

    const float* yp = g_yT + (size_t)bf * 256 * HWS;
    #pragma unroll
    for (int c0 = 0; c0 < 256; c0 += 8) {
        int c = c0 + ty;
        sm[c][tx] = yp[(size_t)c * HWS + hw0 + tx];
    }
    __syncthreads();

    float s = 0.f, sq = 0.f;
    #pragma unroll
    for (int k = 0; k < 32; k++) {
        float v = sm[ty * 32 + k][tx];
        s += v; sq += v * v;
    }
    psum[ty][tx] = s; psq[ty][tx] = sq;
    __syncthreads();

    if (ty == 0) {
        float S = 0.f, Q = 0.f;
        #pragma unroll
        for (int k = 0; k < 8; k++) { S += psum[k][tx]; Q += psq[k][tx]; }
        float m   = S * (1.f / 256.f);
        float var = Q * (1.f / 256.f) - m * m;
        mu[tx] = m;
        rs[tx] = rsqrtf(var + 1e-5f);
    }
    __syncthreads();

    int tokl = tid >> 3, cg = tid & 7;
    int tok  = bf * HWS + hw0 + tokl;
    float m = mu[tokl], r = rs[tokl];
    size_t rowoff = (size_t)tok * 256;
    #pragma unroll
    for (int k = 0; k < 32; k++) {
        int c = k * 8 + cg;
        float v = sm[c][tokl];
        g_tn_bf[rowoff + c] = __float2bfloat16_rn((v - m) * r * gam[c] + bet[c]);
    }
}

// ---------------------------------------------------------------------------
// MLP GEMM1 + exact GELU -> g_hid_bf (bf16 token-major)
// ---------------------------------------------------------------------------
__global__ __launch_bounds__(256, 2) void mlp1_mm(const float* __restrict__ b1)
{
    extern __shared__ __align__(1024) char dsm[];
    uint32_t sbase = smem_u32(dsm);
    int m0 = blockIdx.y * 128, n0 = blockIdx.x * 128;

    float acc[4][4][4];
    wgemm(g_tn_bf, 256, g_w1, 256, m0, n0, 4, sbase, acc);

    const int lane = threadIdx.x & 31, w = threadIdx.x >> 5;
    const int wm = (w & 1) * 64, wn = (w >> 1) * 32;
    const int g = lane >> 2, tq = lane & 3;
    #pragma unroll
    for (int fm = 0; fm < 4; fm++)
        #pragma unroll
        for (int i2 = 0; i2 < 2; i2++) {
            int ml = wm + fm * 16 + g + i2 * 8;
            #pragma unroll
            for (int fn = 0; fn < 4; fn++) {
                int ol = wn + fn * 8 + tq * 2;
                int o  = n0 + ol;
                float h0 = acc[fm][fn][i2 * 2]     + __ldg(b1 + o);
                float h1 = acc[fm][fn][i2 * 2 + 1] + __ldg(b1 + o + 1);
                float gl0 = 0.5f * h0 * (1.f + erff(h0 * 0.70710678118654752f));
                float gl1 = 0.5f * h1 * (1.f + erff(h1 * 0.70710678118654752f));
                __nv_bfloat162 p = __floats2bfloat162_rn(gl0, gl1);
                *(uint32_t*)(dsm + ml * 272 + ol * 2) = *(uint32_t*)&p;
            }
        }
    __syncthreads();

    int row = threadIdx.x >> 1, half = threadIdx.x & 1;
    __nv_bfloat16* dst = g_hid_bf + (size_t)(m0 + row) * 1024 + n0 + half * 64;
    const char* src = dsm + row * 272 + half * 128;
    #pragma unroll
    for (int j = 0; j < 8; j++)
        *(uint4*)(dst + j * 8) = *(const uint4*)(src + j * 16);
}

// ---------------------------------------------------------------------------
// MLP GEMM2 + residual (g_yT) + channel-major store to out (B,F,C,H,W)
// ---------------------------------------------------------------------------
__global__ __launch_bounds__(256, 2) void mlp2_mm(
    const float* __restrict__ b2, float* __restrict__ out)
{
    extern __shared__ __align__(1024) char dsm[];
    uint32_t sbase = smem_u32(dsm);
    int m0 = blockIdx.y * 128, n0 = blockIdx.x * 128;
    int bfi = m0 >> 12, hw0 = m0 & 4095;

    float acc[4][4][4];
    wgemm(g_hid_bf, 1024, g_w2, 1024, m0, n0, 16, sbase, acc);

    float* Rs = reinterpret_cast<float*>(dsm);
    {
        int tid = threadIdx.x;
        #pragma unroll
        for (int it = 0; it < 16; it++) {
            int idx = it * 256 + tid;
            int c = idx >> 5, hw4 = idx & 31;
            float4 v = *reinterpret_cast<const float4*>(
                g_yT + ((size_t)bfi * 256 + n0 + c) * 4096 + hw0 + hw4 * 4);
            *reinterpret_cast<float4*>(Rs + c * 132 + hw4 * 4) = v;
        }
    }
    __syncthreads();

    const int lane = threadIdx.x & 31, w = threadIdx.x >> 5;
    const int wm = (w & 1) * 64, wn = (w >> 1) * 32;
    const int g = lane >> 2, tq = lane & 3;
    #pragma unroll
    for (int fm = 0; fm < 4; fm++)
        #pragma unroll
        for (int fn = 0; fn < 4; fn++) {
            int ol = wn + fn * 8 + tq * 2;
            float b0 = __ldg(b2 + n0 + ol), b1 = __ldg(b2 + n0 + ol + 1);
            #pragma unroll
            for (int i2 = 0; i2 < 2; i2++) {
                int ml = wm + fm * 16 + g + i2 * 8;
                Rs[ol * 132 + ml]       += acc[fm][fn][i2*2]   + b0;
                Rs[(ol + 1) * 132 + ml] += acc[fm][fn][i2*2+1] + b1;
            }
        }
    __syncthreads();

    {
        int tid = threadIdx.x;
        #pragma unroll
        for (int it = 0; it < 16; it++) {
            int idx = it * 256 + tid;
            int c = idx >> 5, hw4 = idx & 31;
            float4 v = *reinterpret_cast<const float4*>(Rs + c * 132 + hw4 * 4);
            *reinterpret_cast<float4*>(
                out + ((size_t)bfi * 256 + n0 + c) * 4096 + hw0 + hw4 * 4) = v;
        }
    }
}

// ---------------------------------------------------------------------------
extern "C" void kernel_launch(void* const* d_in, const int* in_sizes, int n_in,
                              void* d_out, int out_size)
{
    const float* x     = (const float*)d_in[0];
    const float* ln1_g = (const float*)d_in[1];
    const float* ln1_b = (const float*)d_in[2];
    const float* wh    = (const float*)d_in[3];
    const float* bh    = (const float*)d_in[4];
    const float* wv    = (const float*)d_in[5];
    const float* bv    = (const float*)d_in[6];
    const float* wf    = (const float*)d_in[7];
    const float* bf    = (const float*)d_in[8];
    const float* ln2_g = (const float*)d_in[9];
    const float* ln2_b = (const float*)d_in[10];
    const float* w1    = (const float*)d_in[11];
    const float* b1    = (const float*)d_in[12];
    const float* w2    = (const float*)d_in[13];
    const float* b2    = (const float*)d_in[14];
    float* out = (float*)d_out;

    cudaFuncSetAttribute(qkv_mm,  cudaFuncAttributeMaxDynamicSharedMemorySize, SMEM_DYN128);
    cudaFuncSetAttribute(proj_mm, cudaFuncAttributeMaxDynamicSharedMemorySize, SMEM_DYN128);
    cudaFuncSetAttribute(mlp1_mm, cudaFuncAttributeMaxDynamicSharedMemorySize, SMEM_DYN128);
    cudaFuncSetAttribute(mlp2_mm, cudaFuncAttributeMaxDynamicSharedMemorySize, SMEM_DYN128);

    cvt_all<<<2688, 256>>>(wh, wv, wf, w1, w2);
    ln1_kernel<<<dim3(128, 10), 256>>>(x, ln1_g, ln1_b);
    qkv_mm    <<<dim3(3, 320, 2), 256, SMEM_DYN128>>>(bh, bv);
    attn_kernel<<<2048, 256>>>();
    proj_mm   <<<dim3(2, 320), 256, SMEM_DYN128>>>(x, bf);
    ln2_kernel<<<dim3(128, 10), 256>>>(ln2_g, ln2_b);
    mlp1_mm   <<<dim3(8, 320), 256, SMEM_DYN128>>>(b1);
    mlp2_mm   <<<dim3(2, 320), 256, SMEM_DYN128>>>(b2, out);
}

// round 16
// speedup vs baseline: 1.1328x; 1.0873x over previous
#include <cuda_runtime.h>
#include <cuda_bf16.h>
#include <math.h>
#include <cstdint>

#define HWS  4096
#define TOK  40960
#define QKV_HALF (TOK*384)

// ---------------------------------------------------------------------------
// Static device scratch
// ---------------------------------------------------------------------------
__device__ __nv_bfloat16 g_xn_bf [TOK*256];
__device__ __nv_bfloat16 g_qkv_bf[2*QKV_HALF];
__device__ __nv_bfloat16 g_ao_bf [TOK*256];
__device__ float         g_yT    [TOK*256];
__device__ __nv_bfloat16 g_tn_bf [TOK*256];
__device__ __nv_bfloat16 g_hid_bf[TOK*1024];
__device__ __nv_bfloat16 g_wh[384*128];
__device__ __nv_bfloat16 g_wv[384*128];
__device__ __nv_bfloat16 g_wf[256*256];
__device__ __nv_bfloat16 g_w1[1024*256];
__device__ __nv_bfloat16 g_w2[256*1024];

#define SMEM_SWIZZLE_128B(byte_offset) \
    ((byte_offset) ^ (((byte_offset) >> 3) & 0x70))

#define SMEM_DYN64 73728      // 3 stages x (16KB A + 8KB B)

// ---------------------------------------------------------------------------
// Baseline-ISA building blocks
// ---------------------------------------------------------------------------
__device__ __forceinline__ void mma16816(float d[4], const uint32_t a[4],
                                         uint32_t b0, uint32_t b1)
{
    asm volatile(
        "mma.sync.aligned.m16n8k16.row.col.f32.bf16.bf16.f32 "
        "{%0,%1,%2,%3},{%4,%5,%6,%7},{%8,%9},{%0,%1,%2,%3};"
        : "+f"(d[0]), "+f"(d[1]), "+f"(d[2]), "+f"(d[3])
        : "r"(a[0]), "r"(a[1]), "r"(a[2]), "r"(a[3]), "r"(b0), "r"(b1));
}
__device__ __forceinline__ void ldsm_x4(uint32_t r[4], uint32_t addr)
{
    asm volatile("ldmatrix.sync.aligned.m8n8.x4.shared.b16 {%0,%1,%2,%3}, [%4];"
        : "=r"(r[0]), "=r"(r[1]), "=r"(r[2]), "=r"(r[3]) : "r"(addr));
}
__device__ __forceinline__ void cp_async16(uint32_t saddr, const void* g)
{
    asm volatile("cp.async.cg.shared.global [%0], [%1], 16;" :: "r"(saddr), "l"(g));
}
__device__ __forceinline__ void cp_async16_ca(uint32_t saddr, const void* g)
{
    asm volatile("cp.async.ca.shared.global [%0], [%1], 16;" :: "r"(saddr), "l"(g));
}
__device__ __forceinline__ void cp_commit()
{
    asm volatile("cp.async.commit_group;");
}
template<int N> __device__ __forceinline__ void cp_wait()
{
    asm volatile("cp.async.wait_group %0;" :: "n"(N));
}
__device__ __forceinline__ uint32_t smem_u32(const void* p)
{
    uint32_t a;
    asm("{ .reg .u64 t; cvta.to.shared.u64 t, %1; cvt.u32.u64 %0, t; }"
        : "=r"(a) : "l"(p));
    return a;
}

// ---------------------------------------------------------------------------
// 128x64 warp-MMA GEMM (8 warps, warp tile 32x32), 3-stage cp.async,
// designed for occupancy 3 (24 warps/SM). .ca on weights.
// acc[fm][fn][i]: m = wm+fm*16+g+8*(i>>1), n = wn+fn*8+tq*2+(i&1)
//   wm = (w&3)*32, wn = (w>>2)*32
// ---------------------------------------------------------------------------
__device__ __forceinline__ void wgemm64(
    const __nv_bfloat16* __restrict__ A, int lda,
    const __nv_bfloat16* __restrict__ B, int ldb,
    int m0, int n0, int nchunks, uint32_t sbase,
    float (&acc)[2][4][4])
{
    const int tid  = threadIdx.x;
    const int lane = tid & 31;
    const int w    = tid >> 5;
    const int wm   = (w & 3) * 32;
    const int wn   = (w >> 2) * 32;
    const int r_ld = tid >> 3;
    const int cc_ld = tid & 7;

    const int a_row = (lane & 7) + ((lane >> 3) & 1) * 8;
    const int a_k16 = ((lane >> 4) & 1) * 16;
    const int b_row = (lane & 7) + ((lane >> 4) & 1) * 8;
    const int b_k16 = ((lane >> 3) & 1) * 16;

    #pragma unroll
    for (int fm = 0; fm < 2; fm++)
        #pragma unroll
        for (int fn = 0; fn < 4; fn++)
            #pragma unroll
            for (int i = 0; i < 4; i++) acc[fm][fn][i] = 0.f;

    auto issue = [&](int c) {
        int s = c % 3;
        int k0 = c << 6;
        uint32_t base = sbase + s * 24576;
        uint32_t off = SMEM_SWIZZLE_128B((uint32_t)(r_ld * 128 + cc_ld * 16));
        #pragma unroll
        for (int it = 0; it < 4; it++) {
            int r = it * 32 + r_ld;
            cp_async16(base + it * 4096 + off,
                       A + (size_t)(m0 + r) * lda + k0 + cc_ld * 8);
        }
        #pragma unroll
        for (int it = 0; it < 2; it++) {
            int r = it * 32 + r_ld;
            cp_async16_ca(base + 16384 + it * 4096 + off,
                          B + (size_t)(n0 + r) * ldb + k0 + cc_ld * 8);
        }
        cp_commit();
    };

    issue(0);
    if (nchunks > 1) issue(1);

    for (int c = 0; c < nchunks; c++) {
        if (c + 2 < nchunks) { issue(c + 2); cp_wait<2>(); }
        else if (c + 1 < nchunks) cp_wait<1>();
        else cp_wait<0>();
        __syncthreads();

        uint32_t Ab = sbase + (c % 3) * 24576;
        uint32_t Bb = Ab + 16384;
        #pragma unroll
        for (int ks = 0; ks < 4; ks++) {
            int kb = ks * 32;
            uint32_t a[2][4];
            #pragma unroll
            for (int fm = 0; fm < 2; fm++) {
                int r = wm + fm * 16 + a_row;
                ldsm_x4(a[fm], Ab + SMEM_SWIZZLE_128B((uint32_t)(r * 128 + kb + a_k16)));
            }
            uint32_t bfr[2][4];
            #pragma unroll
            for (int fp = 0; fp < 2; fp++) {
                int rn = wn + fp * 16 + b_row;
                ldsm_x4(bfr[fp], Bb + SMEM_SWIZZLE_128B((uint32_t)(rn * 128 + kb + b_k16)));
            }
            #pragma unroll
            for (int fn = 0; fn < 4; fn++) {
                uint32_t b0 = bfr[fn >> 1][(fn & 1) * 2];
                uint32_t b1 = bfr[fn >> 1][(fn & 1) * 2 + 1];
                #pragma unroll
                for (int fm = 0; fm < 2; fm++)
                    mma16816(acc[fm][fn], a[fm], b0, b1);
            }
        }
        __syncthreads();
    }
}

// ---------------------------------------------------------------------------
// LN1
// ---------------------------------------------------------------------------
__global__ __launch_bounds__(256) void ln1_kernel(
    const float* __restrict__ x,
    const float* __restrict__ gam,
    const float* __restrict__ bet)
{
    __shared__ float sm[256][33];
    __shared__ float psum[8][32], psq[8][32];
    __shared__ float mu[32], rs[32];

    int bf  = blockIdx.y;
    int hw0 = blockIdx.x * 32;
    int tid = threadIdx.x;
    int tx  = tid & 31, ty = tid >> 5;

    const float* xp = x + (size_t)bf * 256 * HWS;
    #pragma unroll
    for (int c0 = 0; c0 < 256; c0 += 8) {
        int c = c0 + ty;
        sm[c][tx] = xp[(size_t)c * HWS + hw0 + tx];
    }
    __syncthreads();

    float s = 0.f, sq = 0.f;
    #pragma unroll
    for (int k = 0; k < 32; k++) {
        float v = sm[ty * 32 + k][tx];
        s += v; sq += v * v;
    }
    psum[ty][tx] = s; psq[ty][tx] = sq;
    __syncthreads();

    if (ty == 0) {
        float S = 0.f, Q = 0.f;
        #pragma unroll
        for (int k = 0; k < 8; k++) { S += psum[k][tx]; Q += psq[k][tx]; }
        float m   = S * (1.f / 256.f);
        float var = Q * (1.f / 256.f) - m * m;
        mu[tx] = m;
        rs[tx] = rsqrtf(var + 1e-5f);
    }
    __syncthreads();

    int tokl = tid >> 3, cg = tid & 7;
    int tok  = bf * HWS + hw0 + tokl;
    float m = mu[tokl], r = rs[tokl];
    size_t rowoff = (size_t)tok * 256;
    #pragma unroll
    for (int k = 0; k < 32; k++) {
        int c = k * 8 + cg;
        float v = sm[c][tokl];
        g_xn_bf[rowoff + c] = __float2bfloat16_rn((v - m) * r * gam[c] + bet[c]);
    }
}

// ---------------------------------------------------------------------------
__global__ __launch_bounds__(256) void cvt_all(
    const float* __restrict__ wh, const float* __restrict__ wv,
    const float* __restrict__ wf, const float* __restrict__ w1,
    const float* __restrict__ w2)
{
    int i = blockIdx.x * 256 + threadIdx.x;
    if (i < 49152)        g_wh[i]          = __float2bfloat16_rn(wh[i]);
    else if (i < 98304)   g_wv[i - 49152]  = __float2bfloat16_rn(wv[i - 49152]);
    else if (i < 163840)  g_wf[i - 98304]  = __float2bfloat16_rn(wf[i - 98304]);
    else if (i < 425984)  g_w1[i - 163840] = __float2bfloat16_rn(w1[i - 163840]);
    else if (i < 688128)  g_w2[i - 425984] = __float2bfloat16_rn(w2[i - 425984]);
}

// ---------------------------------------------------------------------------
// QKV GEMM (128x64 tiles) -> token-major g_qkv_bf[branch][t][384]
// ---------------------------------------------------------------------------
__global__ __launch_bounds__(256, 3) void qkv_mm(
    const float* __restrict__ bh, const float* __restrict__ bv)
{
    extern __shared__ __align__(1024) char dsm[];
    uint32_t sbase = smem_u32(dsm);
    int branch = blockIdx.z;
    int m0 = blockIdx.y * 128, n0 = blockIdx.x * 64;
    const __nv_bfloat16* A = g_xn_bf + branch * 128;
    const __nv_bfloat16* W = branch ? g_wv : g_wh;
    const float* bias = branch ? bv : bh;

    float acc[2][4][4];
    wgemm64(A, 256, W, 128, m0, n0, 2, sbase, acc);

    // stage bf16 tile [m][64], stride 72 bf16 (144B rows)
    const int lane = threadIdx.x & 31, w = threadIdx.x >> 5;
    const int wm = (w & 3) * 32, wn = (w >> 2) * 32;
    const int g = lane >> 2, tq = lane & 3;
    #pragma unroll
    for (int fm = 0; fm < 2; fm++)
        #pragma unroll
        for (int i2 = 0; i2 < 2; i2++) {
            int ml = wm + fm * 16 + g + i2 * 8;
            #pragma unroll
            for (int fn = 0; fn < 4; fn++) {
                int ol = wn + fn * 8 + tq * 2;
                int o  = n0 + ol;
                float v0 = acc[fm][fn][i2 * 2]     + __ldg(bias + o);
                float v1 = acc[fm][fn][i2 * 2 + 1] + __ldg(bias + o + 1);
                __nv_bfloat162 p = __floats2bfloat162_rn(v0, v1);
                *(uint32_t*)(dsm + ml * 144 + ol * 2) = *(uint32_t*)&p;
            }
        }
    __syncthreads();

    int row = threadIdx.x >> 1, half = threadIdx.x & 1;
    size_t t = (size_t)m0 + row;
    __nv_bfloat16* dst = g_qkv_bf + (size_t)branch * QKV_HALF + t * 384 + n0 + half * 32;
    const char* src = dsm + row * 144 + half * 64;
    #pragma unroll
    for (int j = 0; j < 4; j++)
        *(uint4*)(dst + j * 8) = *(const uint4*)(src + j * 16);
}

// ---------------------------------------------------------------------------
// Attention (R15 version: quad-shuffle + smem two-stage reduction)
// ---------------------------------------------------------------------------
__global__ __launch_bounds__(256) void attn_kernel()
{
    int id   = blockIdx.x;
    int dir  = id >> 10;
    int b    = (id >> 9) & 1;
    int n    = (id >> 6) & 7;
    int l    = id & 63;

    int tid = threadIdx.x;
    int dd  = tid >> 2;
    int dq  = (tid & 3) * 4;

    const __nv_bfloat16* buf = g_qkv_bf + (size_t)dir * QKV_HALF;
    int hw = dir ? dd * 64 + l : l * 64 + dd;
    int oq = n * 16 + dq;

    float4 q[5], k[5];
    #pragma unroll
    for (int i = 0; i < 5; i++) {
        size_t t = ((size_t)(b * 5 + i) * 4096 + hw) * 384;
        uint2 rq = *reinterpret_cast<const uint2*>(buf + t + oq);
        uint2 rk = *reinterpret_cast<const uint2*>(buf + t + 128 + oq);
        float2 q0 = __bfloat1622float2(*reinterpret_cast<__nv_bfloat162*>(&rq.x));
        float2 q1 = __bfloat1622float2(*reinterpret_cast<__nv_bfloat162*>(&rq.y));
        float2 k0 = __bfloat1622float2(*reinterpret_cast<__nv_bfloat162*>(&rk.x));
        float2 k1 = __bfloat1622float2(*reinterpret_cast<__nv_bfloat162*>(&rk.y));
        q[i] = make_float4(q0.x, q0.y, q1.x, q1.y);
        k[i] = make_float4(k0.x, k0.y, k1.x, k1.y);
    }
    float p[25];
    #pragma unroll
    for (int i = 0; i < 5; i++)
        #pragma unroll
        for (int j = 0; j < 5; j++) {
            float4 a = q[i], c = k[j];
            p[i*5+j] = a.x*c.x + a.y*c.y + a.z*c.z + a.w*c.w;
        }

    #pragma unroll
    for (int e = 0; e < 25; e++) {
        p[e] += __shfl_xor_sync(0xffffffffu, p[e], 1);
        p[e] += __shfl_xor_sync(0xffffffffu, p[e], 2);
    }
    __shared__ float sq_s[64][26];
    if ((tid & 3) == 0) {
        #pragma unroll
        for (int e = 0; e < 25; e++) sq_s[dd][e] = p[e];
    }
    __syncthreads();

    __shared__ float red[25][8];
    if (tid < 200) {
        int e = tid >> 3, grp = tid & 7;
        float s = 0.f;
        #pragma unroll
        for (int kk = 0; kk < 8; kk++) s += sq_s[grp * 8 + kk][e];
        red[e][grp] = s;
    }
    __syncthreads();

    __shared__ float P[5][5];
    if (tid < 5) {
        float srow[5];
        float mx = -1e30f;
        #pragma unroll
        for (int j = 0; j < 5; j++) {
            float s = 0.f;
            #pragma unroll
            for (int wdx = 0; wdx < 8; wdx++) s += red[tid*5+j][wdx];
            s *= (1.f / 32.f);
            srow[j] = s; mx = fmaxf(mx, s);
        }
        float se = 0.f;
        #pragma unroll
        for (int j = 0; j < 5; j++) { srow[j] = __expf(srow[j] - mx); se += srow[j]; }
        float inv = 1.f / se;
        #pragma unroll
        for (int j = 0; j < 5; j++) P[tid][j] = srow[j] * inv;
    }
    __syncthreads();

    float4 o[5];
    #pragma unroll
    for (int i = 0; i < 5; i++) o[i] = make_float4(0.f, 0.f, 0.f, 0.f);
    #pragma unroll
    for (int j = 0; j < 5; j++) {
        size_t t = ((size_t)(b * 5 + j) * 4096 + hw) * 384;
        uint2 rv = *reinterpret_cast<const uint2*>(buf + t + 256 + oq);
        float2 v0 = __bfloat1622float2(*reinterpret_cast<__nv_bfloat162*>(&rv.x));
        float2 v1 = __bfloat1622float2(*reinterpret_cast<__nv_bfloat162*>(&rv.y));
        #pragma unroll
        for (int i = 0; i < 5; i++) {
            float pij = P[i][j];
            o[i].x = fmaf(pij, v0.x, o[i].x);
            o[i].y = fmaf(pij, v0.y, o[i].y);
            o[i].z = fmaf(pij, v1.x, o[i].z);
            o[i].w = fmaf(pij, v1.y, o[i].w);
        }
    }

    int c = dir ? (128 + n * 16 + dq) : (n * 16 + dq);
    #pragma unroll
    for (int fi = 0; fi < 5; fi++) {
        size_t tok = (size_t)(b * 5 + fi) * 4096 + hw;
        __nv_bfloat162 lo = __floats2bfloat162_rn(o[fi].x, o[fi].y);
        __nv_bfloat162 hi = __floats2bfloat162_rn(o[fi].z, o[fi].w);
        uint2 packed;
        packed.x = *reinterpret_cast<uint32_t*>(&lo);
        packed.y = *reinterpret_cast<uint32_t*>(&hi);
        *reinterpret_cast<uint2*>(g_ao_bf + tok * 256 + c) = packed;
    }
}

// ---------------------------------------------------------------------------
// proj (128x64) + residual from x -> g_yT (channel-major)
// ---------------------------------------------------------------------------
__global__ __launch_bounds__(256, 3) void proj_mm(
    const float* __restrict__ x, const float* __restrict__ bfp)
{
    extern __shared__ __align__(1024) char dsm[];
    uint32_t sbase = smem_u32(dsm);
    int m0 = blockIdx.y * 128, n0 = blockIdx.x * 64;
    int bfi = m0 >> 12, hw0 = m0 & 4095;

    float acc[2][4][4];
    wgemm64(g_ao_bf, 256, g_wf, 256, m0, n0, 4, sbase, acc);

    // stage residual from x: Rs[c][m] for 64 channels, stride 132
    float* Rs = reinterpret_cast<float*>(dsm);
    {
        int tid = threadIdx.x;
        #pragma unroll
        for (int it = 0; it < 8; it++) {
            int idx = it * 256 + tid;
            int c = idx >> 5, hw4 = idx & 31;
            float4 v = *reinterpret_cast<const float4*>(
                x + ((size_t)bfi * 256 + n0 + c) * 4096 + hw0 + hw4 * 4);
            *reinterpret_cast<float4*>(Rs + c * 132 + hw4 * 4) = v;
        }
    }
    __syncthreads();

    const int lane = threadIdx.x & 31, w = threadIdx.x >> 5;
    const int wm = (w & 3) * 32, wn = (w >> 2) * 32;
    const int g = lane >> 2, tq = lane & 3;
    #pragma unroll
    for (int fm = 0; fm < 2; fm++)
        #pragma unroll
        for (int fn = 0; fn < 4; fn++) {
            int ol = wn + fn * 8 + tq * 2;
            float b0 = __ldg(bfp + n0 + ol), b1 = __ldg(bfp + n0 + ol + 1);
            #pragma unroll
            for (int i2 = 0; i2 < 2; i2++) {
                int ml = wm + fm * 16 + g + i2 * 8;
                Rs[ol * 132 + ml]       += acc[fm][fn][i2*2]   + b0;
                Rs[(ol + 1) * 132 + ml] += acc[fm][fn][i2*2+1] + b1;
            }
        }
    __syncthreads();

    {
        int tid = threadIdx.x;
        #pragma unroll
        for (int it = 0; it < 8; it++) {
            int idx = it * 256 + tid;
            int c = idx >> 5, hw4 = idx & 31;
            float4 v = *reinterpret_cast<const float4*>(Rs + c * 132 + hw4 * 4);
            *reinterpret_cast<float4*>(
                g_yT + ((size_t)bfi * 256 + n0 + c) * 4096 + hw0 + hw4 * 4) = v;
        }
    }
}

// ---------------------------------------------------------------------------
// LN2: g_yT (channel-major fp32) -> g_tn_bf (token-major bf16).
// ---------------------------------------------------------------------------
__global__ __launch_bounds__(256) void ln2_kernel(
    const float* __restrict__ gam, const float* __restrict__ bet)
{
    __shared__ float sm[256][33];
    __shared__ float psum[8][32], psq[8][32];
    __shared__ float mu[32], rs[32];

    int bf  = blockIdx.y;
    int hw0 = blockIdx.x * 32;
    int tid = threadIdx.x;
    int tx  = tid & 31, ty = tid >> 5;

    const float* yp = g_yT + (size_t)bf * 256 * HWS;
    #pragma unroll
    for (int c0 = 0; c0 < 256; c0 += 8) {
        int c = c0 + ty;
        sm[c][tx] = yp[(size_t)c * HWS + hw0 + tx];
    }
    __syncthreads();

    float s = 0.f, sq = 0.f;
    #pragma unroll
    for (int k = 0; k < 32; k++) {
        float v = sm[ty * 32 + k][tx];
        s += v; sq += v * v;
    }
    psum[ty][tx] = s; psq[ty][tx] = sq;
    __syncthreads();

    if (ty == 0) {
        float S = 0.f, Q = 0.f;
        #pragma unroll
        for (int k = 0; k < 8; k++) { S += psum[k][tx]; Q += psq[k][tx]; }
        float m   = S * (1.f / 256.f);
        float var = Q * (1.f / 256.f) - m * m;
        mu[tx] = m;
        rs[tx] = rsqrtf(var + 1e-5f);
    }
    __syncthreads();

    int tokl = tid >> 3, cg = tid & 7;
    int tok  = bf * HWS + hw0 + tokl;
    float m = mu[tokl], r = rs[tokl];
    size_t rowoff = (size_t)tok * 256;
    #pragma unroll
    for (int k = 0; k < 32; k++) {
        int c = k * 8 + cg;
        float v = sm[c][tokl];
        g_tn_bf[rowoff + c] = __float2bfloat16_rn((v - m) * r * gam[c] + bet[c]);
    }
}

// ---------------------------------------------------------------------------
// MLP GEMM1 (128x64) + exact GELU -> g_hid_bf
// ---------------------------------------------------------------------------
__global__ __launch_bounds__(256, 3) void mlp1_mm(const float* __restrict__ b1)
{
    extern __shared__ __align__(1024) char dsm[];
    uint32_t sbase = smem_u32(dsm);
    int m0 = blockIdx.y * 128, n0 = blockIdx.x * 64;

    float acc[2][4][4];
    wgemm64(g_tn_bf, 256, g_w1, 256, m0, n0, 4, sbase, acc);

    const int lane = threadIdx.x & 31, w = threadIdx.x >> 5;
    const int wm = (w & 3) * 32, wn = (w >> 2) * 32;
    const int g = lane >> 2, tq = lane & 3;
    #pragma unroll
    for (int fm = 0; fm < 2; fm++)
        #pragma unroll
        for (int i2 = 0; i2 < 2; i2++) {
            int ml = wm + fm * 16 + g + i2 * 8;
            #pragma unroll
            for (int fn = 0; fn < 4; fn++) {
                int ol = wn + fn * 8 + tq * 2;
                int o  = n0 + ol;
                float h0 = acc[fm][fn][i2 * 2]     + __ldg(b1 + o);
                float h1 = acc[fm][fn][i2 * 2 + 1] + __ldg(b1 + o + 1);
                float gl0 = 0.5f * h0 * (1.f + erff(h0 * 0.70710678118654752f));
                float gl1 = 0.5f * h1 * (1.f + erff(h1 * 0.70710678118654752f));
                __nv_bfloat162 p = __floats2bfloat162_rn(gl0, gl1);
                *(uint32_t*)(dsm + ml * 144 + ol * 2) = *(uint32_t*)&p;
            }
        }
    __syncthreads();

    int row = threadIdx.x >> 1, half = threadIdx.x & 1;
    __nv_bfloat16* dst = g_hid_bf + (size_t)(m0 + row) * 1024 + n0 + half * 32;
    const char* src = dsm + row * 144 + half * 64;
    #pragma unroll
    for (int j = 0; j < 4; j++)
        *(uint4*)(dst + j * 8) = *(const uint4*)(src + j * 16);
}

// ---------------------------------------------------------------------------
// MLP GEMM2 (128x64) + residual (g_yT) + channel-major store to out
// ---------------------------------------------------------------------------
__global__ __launch_bounds__(256, 3) void mlp2_mm(
    const float* __restrict__ b2, float* __restrict__ out)
{
    extern __shared__ __align__(1024) char dsm[];
    uint32_t sbase = smem_u32(dsm);
    int m0 = blockIdx.y * 128, n0 = blockIdx.x * 64;
    int bfi = m0 >> 12, hw0 = m0 & 4095;

    float acc[2][4][4];
    wgemm64(g_hid_bf, 1024, g_w2, 1024, m0, n0, 16, sbase, acc);

    float* Rs = reinterpret_cast<float*>(dsm);
    {
        int tid = threadIdx.x;
        #pragma unroll
        for (int it = 0; it < 8; it++) {
            int idx = it * 256 + tid;
            int c = idx >> 5, hw4 = idx & 31;
            float4 v = *reinterpret_cast<const float4*>(
                g_yT + ((size_t)bfi * 256 + n0 + c) * 4096 + hw0 + hw4 * 4);
            *reinterpret_cast<float4*>(Rs + c * 132 + hw4 * 4) = v;
        }
    }
    __syncthreads();

    const int lane = threadIdx.x & 31, w = threadIdx.x >> 5;
    const int wm = (w & 3) * 32, wn = (w >> 2) * 32;
    const int g = lane >> 2, tq = lane & 3;
    #pragma unroll
    for (int fm = 0; fm < 2; fm++)
        #pragma unroll
        for (int fn = 0; fn < 4; fn++) {
            int ol = wn + fn * 8 + tq * 2;
            float b0 = __ldg(b2 + n0 + ol), b1 = __ldg(b2 + n0 + ol + 1);
            #pragma unroll
            for (int i2 = 0; i2 < 2; i2++) {
                int ml = wm + fm * 16 + g + i2 * 8;
                Rs[ol * 132 + ml]       += acc[fm][fn][i2*2]   + b0;
                Rs[(ol + 1) * 132 + ml] += acc[fm][fn][i2*2+1] + b1;
            }
        }
    __syncthreads();

    {
        int tid = threadIdx.x;
        #pragma unroll
        for (int it = 0; it < 8; it++) {
            int idx = it * 256 + tid;
            int c = idx >> 5, hw4 = idx & 31;
            float4 v = *reinterpret_cast<const float4*>(Rs + c * 132 + hw4 * 4);
            *reinterpret_cast<float4*>(
                out + ((size_t)bfi * 256 + n0 + c) * 4096 + hw0 + hw4 * 4) = v;
        }
    }
}

// ---------------------------------------------------------------------------
extern "C" void kernel_launch(void* const* d_in, const int* in_sizes, int n_in,
                              void* d_out, int out_size)
{
    const float* x     = (const float*)d_in[0];
    const float* ln1_g = (const float*)d_in[1];
    const float* ln1_b = (const float*)d_in[2];
    const float* wh    = (const float*)d_in[3];
    const float* bh    = (const float*)d_in[4];
    const float* wv    = (const float*)d_in[5];
    const float* bv    = (const float*)d_in[6];
    const float* wf    = (const float*)d_in[7];
    const float* bf    = (const float*)d_in[8];
    const float* ln2_g = (const float*)d_in[9];
    const float* ln2_b = (const float*)d_in[10];
    const float* w1    = (const float*)d_in[11];
    const float* b1    = (const float*)d_in[12];
    const float* w2    = (const float*)d_in[13];
    const float* b2    = (const float*)d_in[14];
    float* out = (float*)d_out;

    cudaFuncSetAttribute(qkv_mm,  cudaFuncAttributeMaxDynamicSharedMemorySize, SMEM_DYN64);
    cudaFuncSetAttribute(proj_mm, cudaFuncAttributeMaxDynamicSharedMemorySize, SMEM_DYN64);
    cudaFuncSetAttribute(mlp1_mm, cudaFuncAttributeMaxDynamicSharedMemorySize, SMEM_DYN64);
    cudaFuncSetAttribute(mlp2_mm, cudaFuncAttributeMaxDynamicSharedMemorySize, SMEM_DYN64);

    cvt_all<<<2688, 256>>>(wh, wv, wf, w1, w2);
    ln1_kernel<<<dim3(128, 10), 256>>>(x, ln1_g, ln1_b);
    qkv_mm    <<<dim3(6, 320, 2), 256, SMEM_DYN64>>>(bh, bv);
    attn_kernel<<<2048, 256>>>();
    proj_mm   <<<dim3(4, 320), 256, SMEM_DYN64>>>(x, bf);
    ln2_kernel<<<dim3(128, 10), 256>>>(ln2_g, ln2_b);
    mlp1_mm   <<<dim3(16, 320), 256, SMEM_DYN64>>>(b1);
    mlp2_mm   <<<dim3(4, 320), 256, SMEM_DYN64>>>(b2, out);
}